// round 1
// baseline (speedup 1.0000x reference)
#include <cuda_runtime.h>
#include <math.h>

// Problem constants
#define BB 4
#define NN 100
#define TT 20
#define HH 64
#define OO 128
#define MM 40000          // B*N*N edges
#define NE 8              // edges per group
#define NGROUPS (MM/NE)   // 5000
#define ESLOT 22          // per-edge column slot: [0]=left pad, [1..20]=t, [21]=right pad
#define XROW (NE*ESLOT+1) // 177, odd stride for bank spread

// Scratch (module-scope device globals; no runtime allocation)
__device__ float g_efa[MM * HH];   // 10.24 MB
__device__ float g_score[MM];
__device__ float g_attw[MM];
__device__ float g_A1[HH * 3];
__device__ float g_Bb[HH * 3];

// ---------------------------------------------------------------------------
// K0: fold conv1 weights against the rank-1 edge embedding
// A1[h,k] = sum_i w1[h,i,k]*W_edge[i]; Bb[h,k] = sum_i w1[h,i,k]*b_edge[i]
// ---------------------------------------------------------------------------
__global__ void k_prep(const float* __restrict__ w1,
                       const float* __restrict__ We,
                       const float* __restrict__ be) {
    int idx = threadIdx.x;
    if (idx < HH * 3) {
        int h = idx / 3, k = idx % 3;
        float a = 0.f, c = 0.f;
        for (int i = 0; i < HH; ++i) {
            float w = w1[(h * HH + i) * 3 + k];
            a += w * We[i];
            c += w * be[i];
        }
        g_A1[idx] = a;
        g_Bb[idx] = c;
    }
}

// ---------------------------------------------------------------------------
// K2: fused per-edge temporal pipeline.
// Per group of 8 edges: x1 (folded conv1+relu) -> conv2+relu -> temporal
// attention (tanh/Wt1, Wt2, softmax over T) -> efa -> spatial pre-attention
// score. Register-tiled SIMT GEMMs with SMEM-resident weights.
// ---------------------------------------------------------------------------
extern __shared__ float smem[];

__global__ void __launch_bounds__(256, 1) k_edge(
    const float* __restrict__ ew,   const float* __restrict__ b1,
    const float* __restrict__ w2,   const float* __restrict__ b2,
    const float* __restrict__ Wt1,  const float* __restrict__ bt1,
    const float* __restrict__ Wt2,  const float* __restrict__ bt2,
    const float* __restrict__ Ws1,  const float* __restrict__ bs1,
    const float* __restrict__ Ws2,  const float* __restrict__ bs2)
{
    // SMEM carve (floats)
    float* w2s   = smem;             // 12288 : conv2_w transposed [k][i][h]
    float* wt1s  = w2s + 12288;      // 4096  : Wt1 [i][h]
    float* xs    = wt1s + 4096;      // 11328 : x tiles [ch][NE*22] (+pad)
    float* e_s   = xs + 64 * XROW;   // 160   : raw edge scalars
    float* att_s = e_s + 160;        // 160   : temporal attention weights
    float* spart = att_s + 160;      // 320   : score partials (2 h-halves)
    float* efa_s = spart + 320;      // 512   : efa per (e,h)
    float* ss    = efa_s + 512;      // 16    : spatial score partials
    // total = 28880 floats = 115520 B

    const int tid  = threadIdx.x;
    const int w    = tid >> 5;
    const int lane = tid & 31;

    // Load weights into SMEM (one-time per block)
    for (int f = tid; f < 12288; f += 256) {
        int h = f / 192, r = f % 192, i = r / 3, k = r % 3;
        w2s[(k * 64 + i) * 64 + h] = w2[f];
    }
    for (int f = tid; f < 4096; f += 256) wt1s[f] = Wt1[f];
    // Zero the padding columns of xs once (never overwritten)
    for (int f = tid; f < 64 * 2 * NE; f += 256) {
        int i = f / (2 * NE), p = f % (2 * NE);
        int e = p >> 1, side = p & 1;
        xs[i * XROW + e * ESLOT + side * 21] = 0.f;
    }
    __syncthreads();

    // Thread tile mapping: output grid 64h x 160n (n = e*20 + t)
    // warp: h-half = w&1, n-quarter = w>>1; lane: h-group = lane&7 (x4),
    // n-group = lane>>3 (x10)
    const int hh0 = 32 * (w & 1) + 4 * (lane & 7);
    const int n0  = 40 * (w >> 1) + 10 * (lane >> 3);
    const int eL  = n0 / 20, t0 = n0 % 20;
    const int xb  = eL * ESLOT + t0;       // conv2 12-wide window base
    const int xb2 = eL * ESLOT + 1 + t0;   // 10-wide aligned base

    const float hb2[4] = { b2[hh0], b2[hh0+1], b2[hh0+2], b2[hh0+3] };
    const float bt1v[4] = { bt1[hh0], bt1[hh0+1], bt1[hh0+2], bt1[hh0+3] };
    const float wt2v[4] = { Wt2[hh0], Wt2[hh0+1], Wt2[hh0+2], Wt2[hh0+3] };
    const float bt2v = bt2[0];
    const float bs2v = bs2[0];

    for (int g = blockIdx.x; g < NGROUPS; g += gridDim.x) {
        const int m0 = g * NE;
        __syncthreads();  // protect SMEM reuse across groups

        // Load edge scalars
        for (int f = tid; f < NE * TT; f += 256) e_s[f] = ew[m0 * TT + f];
        __syncthreads();

        // x1 = relu(folded conv1): 64ch x 8e x 20t
        for (int idx = tid; idx < 64 * NE * TT; idx += 256) {
            int i = idx / (NE * TT), r = idx % (NE * TT);
            int e = r / TT, t = r % TT;
            float acc = b1[i];
            #pragma unroll
            for (int k = 0; k < 3; ++k) {
                int tv = t + k - 1;
                if (tv >= 0 && tv < TT)
                    acc += g_A1[i * 3 + k] * e_s[e * TT + tv] + g_Bb[i * 3 + k];
            }
            xs[i * XROW + e * ESLOT + 1 + t] = fmaxf(acc, 0.f);
        }
        __syncthreads();

        // conv2: y2[h,t] = b2 + sum_{i,k} x1[i,t+k-1]*w2[h,i,k]
        float acc[4][10];
        #pragma unroll
        for (int j = 0; j < 4; ++j)
            #pragma unroll
            for (int q = 0; q < 10; ++q) acc[j][q] = 0.f;

        #pragma unroll 1
        for (int i = 0; i < 64; ++i) {
            const float* xr = xs + i * XROW + xb;
            float xv[12];
            #pragma unroll
            for (int c = 0; c < 12; ++c) xv[c] = xr[c];
            #pragma unroll
            for (int k = 0; k < 3; ++k) {
                float4 wv = *(const float4*)(w2s + (k * 64 + i) * 64 + hh0);
                #pragma unroll
                for (int q = 0; q < 10; ++q) {
                    float x = xv[q + k];
                    acc[0][q] += wv.x * x;
                    acc[1][q] += wv.y * x;
                    acc[2][q] += wv.z * x;
                    acc[3][q] += wv.w * x;
                }
            }
        }
        __syncthreads();  // all conv2 reads of xs complete

        // x2 = relu(y2 + b2), written back into xs
        #pragma unroll
        for (int j = 0; j < 4; ++j)
            #pragma unroll
            for (int q = 0; q < 10; ++q)
                xs[(hh0 + j) * XROW + xb2 + q] = fmaxf(acc[j][q] + hb2[j], 0.f);
        __syncthreads();

        // u = tanh(x2^T @ Wt1 + bt1); score partial p[t] = sum_h u*Wt2[h]
        float acc2[4][10];
        #pragma unroll
        for (int j = 0; j < 4; ++j)
            #pragma unroll
            for (int q = 0; q < 10; ++q) acc2[j][q] = 0.f;

        #pragma unroll 1
        for (int i = 0; i < 64; ++i) {
            const float* xr = xs + i * XROW + xb2;
            float xv[10];
            #pragma unroll
            for (int c = 0; c < 10; ++c) xv[c] = xr[c];
            float4 wv = *(const float4*)(wt1s + i * 64 + hh0);
            #pragma unroll
            for (int q = 0; q < 10; ++q) {
                acc2[0][q] += wv.x * xv[q];
                acc2[1][q] += wv.y * xv[q];
                acc2[2][q] += wv.z * xv[q];
                acc2[3][q] += wv.w * xv[q];
            }
        }
        float p[10];
        #pragma unroll
        for (int q = 0; q < 10; ++q) {
            float s = 0.f;
            #pragma unroll
            for (int j = 0; j < 4; ++j)
                s += tanhf(acc2[j][q] + bt1v[j]) * wt2v[j];
            p[q] = s;
        }
        // reduce over the 8 h-group lanes
        #pragma unroll
        for (int off = 4; off; off >>= 1)
            #pragma unroll
            for (int q = 0; q < 10; ++q)
                p[q] += __shfl_down_sync(0xffffffffu, p[q], off);
        if ((lane & 7) == 0) {
            #pragma unroll
            for (int q = 0; q < 10; ++q)
                spart[(w & 1) * 160 + n0 + q] = p[q];
        }
        __syncthreads();

        // temporal softmax: warp w handles edge w
        {
            float v = -1e30f;
            if (lane < TT)
                v = spart[w * TT + lane] + spart[160 + w * TT + lane] + bt2v;
            float mx = v;
            #pragma unroll
            for (int off = 16; off; off >>= 1)
                mx = fmaxf(mx, __shfl_xor_sync(0xffffffffu, mx, off));
            float ev = (lane < TT) ? expf(v - mx) : 0.f;
            float sum = ev;
            #pragma unroll
            for (int off = 16; off; off >>= 1)
                sum += __shfl_xor_sync(0xffffffffu, sum, off);
            if (lane < TT) att_s[w * TT + lane] = ev / sum;
        }
        __syncthreads();

        // efa[e,h] = sum_t x2[h,t]*att[t]
        for (int idx = tid; idx < NE * 64; idx += 256) {
            int e = idx >> 6, h = idx & 63;
            const float* xr = xs + h * XROW + e * ESLOT + 1;
            float a = 0.f;
            #pragma unroll
            for (int t = 0; t < TT; ++t) a += xr[t] * att_s[e * TT + t];
            efa_s[idx] = a;
            g_efa[(m0 + e) * 64 + h] = a;
        }
        __syncthreads();

        // spatial pre-attention score per edge: sum_h tanh(efa@Ws1+bs1)*Ws2
        #pragma unroll 1
        for (int it = 0; it < 2; ++it) {
            int idx = it * 256 + tid;
            int e = idx >> 6, h = idx & 63;
            const float* ef = efa_s + e * 64;
            float a = bs1[h];
            #pragma unroll 1
            for (int i = 0; i < 64; ++i) a += ef[i] * Ws1[i * 64 + h];
            float val = tanhf(a) * Ws2[h];
            #pragma unroll
            for (int off = 16; off; off >>= 1)
                val += __shfl_xor_sync(0xffffffffu, val, off);
            if (lane == 0) ss[e * 2 + (w & 1)] = val;  // e = it*4 + (w>>1)
            __syncthreads();
        }
        if (tid < NE) g_score[m0 + tid] = ss[tid * 2] + ss[tid * 2 + 1] + bs2v;
    }
}

// ---------------------------------------------------------------------------
// K3: per-batch spatial softmax over N*N = 10000 scores
// ---------------------------------------------------------------------------
__global__ void __launch_bounds__(1024) k_spatial() {
    __shared__ float red[1024];
    __shared__ float mx_s, z_s;
    int b = blockIdx.x, tid = threadIdx.x;
    const float* sc = g_score + b * (NN * NN);

    float mx = -1e30f;
    for (int i = tid; i < NN * NN; i += 1024) mx = fmaxf(mx, sc[i]);
    red[tid] = mx;
    __syncthreads();
    for (int s = 512; s; s >>= 1) {
        if (tid < s) red[tid] = fmaxf(red[tid], red[tid + s]);
        __syncthreads();
    }
    if (tid == 0) mx_s = red[0];
    __syncthreads();
    float m = mx_s, z = 0.f;
    for (int i = tid; i < NN * NN; i += 1024) z += expf(sc[i] - m);
    red[tid] = z;
    __syncthreads();
    for (int s = 512; s; s >>= 1) {
        if (tid < s) red[tid] += red[tid + s];
        __syncthreads();
    }
    if (tid == 0) z_s = red[0];
    __syncthreads();
    float inv = 1.f / z_s;
    for (int i = tid; i < NN * NN; i += 1024)
        g_attw[b * (NN * NN) + i] = expf(sc[i] - m) * inv;
}

// ---------------------------------------------------------------------------
// K4: node aggregation + 3-layer MLP. One block per (b,i) node.
// ---------------------------------------------------------------------------
__global__ void __launch_bounds__(128) k_node(
    const float* __restrict__ Wg1, const float* __restrict__ bg1,
    const float* __restrict__ Wg2, const float* __restrict__ bg2,
    const float* __restrict__ Wout, const float* __restrict__ bout,
    float* __restrict__ out)
{
    __shared__ float nsm[128], g1s[64], g2s[64];
    const int bi = blockIdx.x;          // b*100 + i
    const int tid = threadIdx.x;
    const int h = tid & 63, half = tid >> 6;

    const float* efa = g_efa + (size_t)bi * NN * HH;
    const float* aw  = g_attw + bi * NN;
    float a = 0.f;
    for (int j = half * 50; j < half * 50 + 50; ++j)
        a += efa[j * 64 + h] * aw[j];
    nsm[tid] = a;
    __syncthreads();
    if (tid < 64) nsm[tid] = nsm[tid] + nsm[tid + 64];
    __syncthreads();
    if (tid < 64) {
        float acc = bg1[tid];
        for (int i = 0; i < 64; ++i) acc += nsm[i] * Wg1[i * 64 + tid];
        g1s[tid] = fmaxf(acc, 0.f);
    }
    __syncthreads();
    if (tid < 64) {
        float acc = bg2[tid];
        for (int i = 0; i < 64; ++i) acc += g1s[i] * Wg2[i * 64 + tid];
        g2s[tid] = fmaxf(acc, 0.f);
    }
    __syncthreads();
    {
        float acc = bout[tid];
        for (int i = 0; i < 64; ++i) acc += g2s[i] * Wout[i * OO + tid];
        out[bi * OO + tid] = fmaxf(acc, 0.f);
    }
}

// ---------------------------------------------------------------------------
extern "C" void kernel_launch(void* const* d_in, const int* in_sizes, int n_in,
                              void* d_out, int out_size) {
    const float* ew   = (const float*)d_in[0];
    const float* We   = (const float*)d_in[1];
    const float* be   = (const float*)d_in[2];
    const float* w1   = (const float*)d_in[3];
    const float* b1   = (const float*)d_in[4];
    const float* w2   = (const float*)d_in[5];
    const float* b2   = (const float*)d_in[6];
    const float* Wt1  = (const float*)d_in[7];
    const float* bt1  = (const float*)d_in[8];
    const float* Wt2  = (const float*)d_in[9];
    const float* bt2  = (const float*)d_in[10];
    const float* Ws1  = (const float*)d_in[11];
    const float* bs1  = (const float*)d_in[12];
    const float* Ws2  = (const float*)d_in[13];
    const float* bs2  = (const float*)d_in[14];
    const float* Wg1  = (const float*)d_in[15];
    const float* bg1  = (const float*)d_in[16];
    const float* Wg2  = (const float*)d_in[17];
    const float* bg2  = (const float*)d_in[18];
    const float* Wout = (const float*)d_in[19];
    const float* bout = (const float*)d_in[20];
    float* out = (float*)d_out;

    const int smem_bytes = 28880 * 4;  // 115520 B
    cudaFuncSetAttribute(k_edge, cudaFuncAttributeMaxDynamicSharedMemorySize,
                         smem_bytes);

    k_prep<<<1, 256>>>(w1, We, be);
    k_edge<<<148, 256, smem_bytes>>>(ew, b1, w2, b2, Wt1, bt1, Wt2, bt2,
                                     Ws1, bs1, Ws2, bs2);
    k_spatial<<<BB, 1024>>>();
    k_node<<<BB * NN, 128>>>(Wg1, bg1, Wg2, bg2, Wout, bout, out);
}

// round 2
// speedup vs baseline: 1.0840x; 1.0840x over previous
#include <cuda_runtime.h>
#include <math.h>

// Problem constants
#define BB 4
#define NN 100
#define TT 20
#define HH 64
#define OO 128
#define MM 40000          // B*N*N edges
#define NE 8              // edges per group
#define NGROUPS (MM/NE)   // 5000
#define ESLOT 22          // per-edge column slot: [0]=left pad, [1..20]=t, [21]=right pad
#define XROW (NE*ESLOT+1) // 177, odd stride for bank spread

// Scratch (module-scope device globals; no runtime allocation)
__device__ float g_efa[MM * HH];   // 10.24 MB
__device__ float g_score[MM];
__device__ float g_attw[MM];
__device__ float g_A1[HH * 3];
__device__ float g_Bb[HH * 3];

// ---- f32x2 packed-FMA helpers (SASS FFMA2, PTX-only) ----------------------
__device__ __forceinline__ unsigned long long pk2(float x, float y) {
    unsigned long long r;
    asm("mov.b64 %0, {%1, %2};" : "=l"(r) : "f"(x), "f"(y));
    return r;
}
__device__ __forceinline__ unsigned long long dup2(float x) {
    unsigned long long r;
    asm("mov.b64 %0, {%1, %1};" : "=l"(r) : "f"(x));
    return r;
}
__device__ __forceinline__ void fma2(unsigned long long& d,
                                     unsigned long long a,
                                     unsigned long long b) {
    asm("fma.rn.f32x2 %0, %1, %2, %0;" : "+l"(d) : "l"(a), "l"(b));
}
__device__ __forceinline__ float2 up2(unsigned long long v) {
    float2 f;
    asm("mov.b64 {%0, %1}, %2;" : "=f"(f.x), "=f"(f.y) : "l"(v));
    return f;
}
// ---- HW tanh (MUFU.TANH, ~5e-4 max err; well under 1e-3 tolerance) --------
__device__ __forceinline__ float tanha(float x) {
    float y;
    asm("tanh.approx.f32 %0, %1;" : "=f"(y) : "f"(x));
    return y;
}

// ---------------------------------------------------------------------------
// K0: fold conv1 weights against the rank-1 edge embedding
// ---------------------------------------------------------------------------
__global__ void k_prep(const float* __restrict__ w1,
                       const float* __restrict__ We,
                       const float* __restrict__ be) {
    int idx = threadIdx.x;
    if (idx < HH * 3) {
        int h = idx / 3, k = idx % 3;
        float a = 0.f, c = 0.f;
        for (int i = 0; i < HH; ++i) {
            float w = w1[(h * HH + i) * 3 + k];
            a += w * We[i];
            c += w * be[i];
        }
        g_A1[idx] = a;
        g_Bb[idx] = c;
    }
}

// ---------------------------------------------------------------------------
// K2: fused per-edge temporal pipeline (f32x2 packed GEMMs + HW tanh).
// ---------------------------------------------------------------------------
extern __shared__ float smem[];

__global__ void __launch_bounds__(256, 1) k_edge(
    const float* __restrict__ ew,   const float* __restrict__ b1,
    const float* __restrict__ w2,   const float* __restrict__ b2,
    const float* __restrict__ Wt1,  const float* __restrict__ bt1,
    const float* __restrict__ Wt2,  const float* __restrict__ bt2,
    const float* __restrict__ Ws1,  const float* __restrict__ bs1,
    const float* __restrict__ Ws2,  const float* __restrict__ bs2)
{
    // SMEM carve (floats)
    float* w2s   = smem;             // 12288 : conv2_w transposed [k][i][h]
    float* wt1s  = w2s + 12288;      // 4096  : Wt1 [i][h]
    float* ws1s  = wt1s + 4096;      // 4096  : Ws1 [i][h]
    float* xs    = ws1s + 4096;      // 11328 : x tiles [ch][NE*22] (+pad)
    float* e_s   = xs + 64 * XROW;   // 160   : raw edge scalars
    float* att_s = e_s + 160;        // 160   : temporal attention weights
    float* spart = att_s + 160;      // 320   : score partials (2 h-halves)
    float* efa_s = spart + 320;      // 512   : efa per (e,h)
    float* ss    = efa_s + 512;      // 16    : spatial score partials
    // total = 32976 floats = 131904 B

    const int tid  = threadIdx.x;
    const int w    = tid >> 5;
    const int lane = tid & 31;

    // Load weights into SMEM (one-time per block)
    for (int f = tid; f < 12288; f += 256) {
        int h = f / 192, r = f % 192, i = r / 3, k = r % 3;
        w2s[(k * 64 + i) * 64 + h] = w2[f];
    }
    for (int f = tid; f < 4096; f += 256) wt1s[f] = Wt1[f];
    for (int f = tid; f < 4096; f += 256) ws1s[f] = Ws1[f];
    // Zero the padding columns of xs once (never overwritten)
    for (int f = tid; f < 64 * 2 * NE; f += 256) {
        int i = f / (2 * NE), p = f % (2 * NE);
        int e = p >> 1, side = p & 1;
        xs[i * XROW + e * ESLOT + side * 21] = 0.f;
    }
    __syncthreads();

    // Thread tile mapping: output grid 64h x 160n (n = e*20 + t)
    const int hh0 = 32 * (w & 1) + 4 * (lane & 7);
    const int n0  = 40 * (w >> 1) + 10 * (lane >> 3);
    const int eL  = n0 / 20, t0 = n0 % 20;
    const int xb  = eL * ESLOT + t0;       // conv2 12-wide window base
    const int xb2 = eL * ESLOT + 1 + t0;   // 10-wide aligned base

    const float hb2[4] = { b2[hh0], b2[hh0+1], b2[hh0+2], b2[hh0+3] };
    const float bt1v[4] = { bt1[hh0], bt1[hh0+1], bt1[hh0+2], bt1[hh0+3] };
    const float wt2v[4] = { Wt2[hh0], Wt2[hh0+1], Wt2[hh0+2], Wt2[hh0+3] };
    const float bt2v = bt2[0];
    const float bs2v = bs2[0];

    for (int g = blockIdx.x; g < NGROUPS; g += gridDim.x) {
        const int m0 = g * NE;
        __syncthreads();  // protect SMEM reuse across groups

        // Load edge scalars
        for (int f = tid; f < NE * TT; f += 256) e_s[f] = ew[m0 * TT + f];
        __syncthreads();

        // x1 = relu(folded conv1): 64ch x 8e x 20t
        for (int idx = tid; idx < 64 * NE * TT; idx += 256) {
            int i = idx / (NE * TT), r = idx % (NE * TT);
            int e = r / TT, t = r % TT;
            float acc = b1[i];
            #pragma unroll
            for (int k = 0; k < 3; ++k) {
                int tv = t + k - 1;
                if (tv >= 0 && tv < TT)
                    acc += g_A1[i * 3 + k] * e_s[e * TT + tv] + g_Bb[i * 3 + k];
            }
            xs[i * XROW + e * ESLOT + 1 + t] = fmaxf(acc, 0.f);
        }
        __syncthreads();

        // conv2: y2[h,t] = b2 + sum_{i,k} x1[i,t+k-1]*w2[h,i,k]  (FFMA2)
        unsigned long long accp[2][10];
        #pragma unroll
        for (int j = 0; j < 2; ++j)
            #pragma unroll
            for (int q = 0; q < 10; ++q) accp[j][q] = 0ull;

        #pragma unroll 1
        for (int i = 0; i < 64; ++i) {
            const float* xr = xs + i * XROW + xb;
            unsigned long long xp[12];
            #pragma unroll
            for (int c = 0; c < 12; ++c) xp[c] = dup2(xr[c]);
            #pragma unroll
            for (int k = 0; k < 3; ++k) {
                // pair layout in memory == packed-f32x2 layout
                const ulonglong2 wv =
                    *(const ulonglong2*)(w2s + (k * 64 + i) * 64 + hh0);
                #pragma unroll
                for (int q = 0; q < 10; ++q) {
                    fma2(accp[0][q], wv.x, xp[q + k]);
                    fma2(accp[1][q], wv.y, xp[q + k]);
                }
            }
        }
        __syncthreads();  // all conv2 reads of xs complete

        // x2 = relu(y2 + b2), written back into xs
        #pragma unroll
        for (int q = 0; q < 10; ++q) {
            float2 a01 = up2(accp[0][q]);
            float2 a23 = up2(accp[1][q]);
            xs[(hh0 + 0) * XROW + xb2 + q] = fmaxf(a01.x + hb2[0], 0.f);
            xs[(hh0 + 1) * XROW + xb2 + q] = fmaxf(a01.y + hb2[1], 0.f);
            xs[(hh0 + 2) * XROW + xb2 + q] = fmaxf(a23.x + hb2[2], 0.f);
            xs[(hh0 + 3) * XROW + xb2 + q] = fmaxf(a23.y + hb2[3], 0.f);
        }
        __syncthreads();

        // u = tanh(x2^T @ Wt1 + bt1); score partial p[t] = sum_h u*Wt2[h]
        unsigned long long acc2p[2][10];
        #pragma unroll
        for (int j = 0; j < 2; ++j)
            #pragma unroll
            for (int q = 0; q < 10; ++q) acc2p[j][q] = 0ull;

        #pragma unroll 1
        for (int i = 0; i < 64; ++i) {
            const float* xr = xs + i * XROW + xb2;
            unsigned long long xp[10];
            #pragma unroll
            for (int c = 0; c < 10; ++c) xp[c] = dup2(xr[c]);
            const ulonglong2 wv = *(const ulonglong2*)(wt1s + i * 64 + hh0);
            #pragma unroll
            for (int q = 0; q < 10; ++q) {
                fma2(acc2p[0][q], wv.x, xp[q]);
                fma2(acc2p[1][q], wv.y, xp[q]);
            }
        }
        float p[10];
        #pragma unroll
        for (int q = 0; q < 10; ++q) {
            float2 a01 = up2(acc2p[0][q]);
            float2 a23 = up2(acc2p[1][q]);
            float s = tanha(a01.x + bt1v[0]) * wt2v[0]
                    + tanha(a01.y + bt1v[1]) * wt2v[1]
                    + tanha(a23.x + bt1v[2]) * wt2v[2]
                    + tanha(a23.y + bt1v[3]) * wt2v[3];
            p[q] = s;
        }
        // reduce over the 8 h-group lanes
        #pragma unroll
        for (int off = 4; off; off >>= 1)
            #pragma unroll
            for (int q = 0; q < 10; ++q)
                p[q] += __shfl_down_sync(0xffffffffu, p[q], off);
        if ((lane & 7) == 0) {
            #pragma unroll
            for (int q = 0; q < 10; ++q)
                spart[(w & 1) * 160 + n0 + q] = p[q];
        }
        __syncthreads();

        // temporal softmax: warp w handles edge w
        {
            float v = -1e30f;
            if (lane < TT)
                v = spart[w * TT + lane] + spart[160 + w * TT + lane] + bt2v;
            float mx = v;
            #pragma unroll
            for (int off = 16; off; off >>= 1)
                mx = fmaxf(mx, __shfl_xor_sync(0xffffffffu, mx, off));
            float ev = (lane < TT) ? expf(v - mx) : 0.f;
            float sum = ev;
            #pragma unroll
            for (int off = 16; off; off >>= 1)
                sum += __shfl_xor_sync(0xffffffffu, sum, off);
            if (lane < TT) att_s[w * TT + lane] = ev / sum;
        }
        __syncthreads();

        // efa[e,h] = sum_t x2[h,t]*att[t]
        for (int idx = tid; idx < NE * 64; idx += 256) {
            int e = idx >> 6, h = idx & 63;
            const float* xr = xs + h * XROW + e * ESLOT + 1;
            float a = 0.f;
            #pragma unroll
            for (int t = 0; t < TT; ++t) a += xr[t] * att_s[e * TT + t];
            efa_s[idx] = a;
            g_efa[(m0 + e) * 64 + h] = a;
        }
        __syncthreads();

        // spatial pre-attention score per edge: sum_h tanh(efa@Ws1+bs1)*Ws2
        #pragma unroll 1
        for (int it = 0; it < 2; ++it) {
            int idx = it * 256 + tid;
            int e = idx >> 6, h = idx & 63;
            const float* ef = efa_s + e * 64;
            float a = bs1[h];
            #pragma unroll 1
            for (int i = 0; i < 64; ++i) a += ef[i] * ws1s[i * 64 + h];
            float val = tanha(a) * Ws2[h];
            #pragma unroll
            for (int off = 16; off; off >>= 1)
                val += __shfl_xor_sync(0xffffffffu, val, off);
            if (lane == 0) ss[e * 2 + (w & 1)] = val;  // e = it*4 + (w>>1)
            __syncthreads();
        }
        if (tid < NE) g_score[m0 + tid] = ss[tid * 2] + ss[tid * 2 + 1] + bs2v;
    }
}

// ---------------------------------------------------------------------------
// K3: per-batch spatial softmax over N*N = 10000 scores
// ---------------------------------------------------------------------------
__global__ void __launch_bounds__(1024) k_spatial() {
    __shared__ float red[1024];
    __shared__ float mx_s, z_s;
    int b = blockIdx.x, tid = threadIdx.x;
    const float* sc = g_score + b * (NN * NN);

    float mx = -1e30f;
    for (int i = tid; i < NN * NN; i += 1024) mx = fmaxf(mx, sc[i]);
    red[tid] = mx;
    __syncthreads();
    for (int s = 512; s; s >>= 1) {
        if (tid < s) red[tid] = fmaxf(red[tid], red[tid + s]);
        __syncthreads();
    }
    if (tid == 0) mx_s = red[0];
    __syncthreads();
    float m = mx_s, z = 0.f;
    for (int i = tid; i < NN * NN; i += 1024) z += expf(sc[i] - m);
    red[tid] = z;
    __syncthreads();
    for (int s = 512; s; s >>= 1) {
        if (tid < s) red[tid] += red[tid + s];
        __syncthreads();
    }
    if (tid == 0) z_s = red[0];
    __syncthreads();
    float inv = 1.f / z_s;
    for (int i = tid; i < NN * NN; i += 1024)
        g_attw[b * (NN * NN) + i] = expf(sc[i] - m) * inv;
}

// ---------------------------------------------------------------------------
// K4: node aggregation + 3-layer MLP. One block per (b,i) node.
// ---------------------------------------------------------------------------
__global__ void __launch_bounds__(128) k_node(
    const float* __restrict__ Wg1, const float* __restrict__ bg1,
    const float* __restrict__ Wg2, const float* __restrict__ bg2,
    const float* __restrict__ Wout, const float* __restrict__ bout,
    float* __restrict__ out)
{
    __shared__ float nsm[128], g1s[64], g2s[64];
    const int bi = blockIdx.x;          // b*100 + i
    const int tid = threadIdx.x;
    const int h = tid & 63, half = tid >> 6;

    const float* efa = g_efa + (size_t)bi * NN * HH;
    const float* aw  = g_attw + bi * NN;
    float a = 0.f;
    for (int j = half * 50; j < half * 50 + 50; ++j)
        a += efa[j * 64 + h] * aw[j];
    nsm[tid] = a;
    __syncthreads();
    if (tid < 64) nsm[tid] = nsm[tid] + nsm[tid + 64];
    __syncthreads();
    if (tid < 64) {
        float acc = bg1[tid];
        for (int i = 0; i < 64; ++i) acc += nsm[i] * Wg1[i * 64 + tid];
        g1s[tid] = fmaxf(acc, 0.f);
    }
    __syncthreads();
    if (tid < 64) {
        float acc = bg2[tid];
        for (int i = 0; i < 64; ++i) acc += g1s[i] * Wg2[i * 64 + tid];
        g2s[tid] = fmaxf(acc, 0.f);
    }
    __syncthreads();
    {
        float acc = bout[tid];
        for (int i = 0; i < 64; ++i) acc += g2s[i] * Wout[i * OO + tid];
        out[bi * OO + tid] = fmaxf(acc, 0.f);
    }
}

// ---------------------------------------------------------------------------
extern "C" void kernel_launch(void* const* d_in, const int* in_sizes, int n_in,
                              void* d_out, int out_size) {
    const float* ew   = (const float*)d_in[0];
    const float* We   = (const float*)d_in[1];
    const float* be   = (const float*)d_in[2];
    const float* w1   = (const float*)d_in[3];
    const float* b1   = (const float*)d_in[4];
    const float* w2   = (const float*)d_in[5];
    const float* b2   = (const float*)d_in[6];
    const float* Wt1  = (const float*)d_in[7];
    const float* bt1  = (const float*)d_in[8];
    const float* Wt2  = (const float*)d_in[9];
    const float* bt2  = (const float*)d_in[10];
    const float* Ws1  = (const float*)d_in[11];
    const float* bs1  = (const float*)d_in[12];
    const float* Ws2  = (const float*)d_in[13];
    const float* bs2  = (const float*)d_in[14];
    const float* Wg1  = (const float*)d_in[15];
    const float* bg1  = (const float*)d_in[16];
    const float* Wg2  = (const float*)d_in[17];
    const float* bg2  = (const float*)d_in[18];
    const float* Wout = (const float*)d_in[19];
    const float* bout = (const float*)d_in[20];
    float* out = (float*)d_out;

    const int smem_bytes = 32976 * 4;  // 131904 B
    cudaFuncSetAttribute(k_edge, cudaFuncAttributeMaxDynamicSharedMemorySize,
                         smem_bytes);

    k_prep<<<1, 256>>>(w1, We, be);
    k_edge<<<148, 256, smem_bytes>>>(ew, b1, w2, b2, Wt1, bt1, Wt2, bt2,
                                     Ws1, bs1, Ws2, bs2);
    k_spatial<<<BB, 1024>>>();
    k_node<<<BB * NN, 128>>>(Wg1, bg1, Wg2, bg2, Wout, bout, out);
}

// round 3
// speedup vs baseline: 1.6020x; 1.4778x over previous
#include <cuda_runtime.h>
#include <math.h>
#include <stdint.h>

// Problem constants
#define BB 4
#define NN 100
#define TT 20
#define HH 64
#define OO 128
#define MM 40000          // B*N*N edges
#define NE 8              // edges per group
#define NGROUPS (MM/NE)   // 5000
#define ESLOT 22          // per-edge column slot: [0]=left pad, [1..20]=t, [21]=right pad
#define XROW (NE*ESLOT+1) // 177, odd stride for bank spread

// Scratch
__device__ float g_efa[MM * HH];   // 10.24 MB
__device__ float g_score[MM];
__device__ float g_attw[MM];
__device__ float g_A1[HH * 3];
__device__ float g_Bb[HH * 3];

// ---- helpers ---------------------------------------------------------------
__device__ __forceinline__ float tanha(float x) {
    float y;
    asm("tanh.approx.f32 %0, %1;" : "=f"(y) : "f"(x));
    return y;
}
__device__ __forceinline__ uint32_t f2tf32(float x) {
    uint32_t r;
    asm("cvt.rna.tf32.f32 %0, %1;" : "=r"(r) : "f"(x));
    return r;
}
// m16n8k8 tf32 MMA. A frag (a0..a3) = (r,c),(r+8,c),(r,c+4),(r+8,c+4);
// B frag b0=(k=lane%4, n=lane/4), b1=(k+4, n);
// D frag = (r,2c'),(r,2c'+1),(r+8,2c'),(r+8,2c'+1), r=lane/4, c'=lane%4.
__device__ __forceinline__ void mma_tf32(float d[4], uint4 a,
                                         uint32_t b0, uint32_t b1) {
    asm volatile(
        "mma.sync.aligned.m16n8k8.row.col.f32.tf32.tf32.f32 "
        "{%0,%1,%2,%3},{%4,%5,%6,%7},{%8,%9},{%0,%1,%2,%3};"
        : "+f"(d[0]), "+f"(d[1]), "+f"(d[2]), "+f"(d[3])
        : "r"(a.x), "r"(a.y), "r"(a.z), "r"(a.w), "r"(b0), "r"(b1));
}

// ---------------------------------------------------------------------------
// K0: fold conv1 weights against the rank-1 edge embedding
// ---------------------------------------------------------------------------
__global__ void k_prep(const float* __restrict__ w1,
                       const float* __restrict__ We,
                       const float* __restrict__ be) {
    int idx = threadIdx.x;
    if (idx < HH * 3) {
        int h = idx / 3, k = idx % 3;
        float a = 0.f, c = 0.f;
        for (int i = 0; i < HH; ++i) {
            float w = w1[(h * HH + i) * 3 + k];
            a += w * We[i];
            c += w * be[i];
        }
        g_A1[idx] = a;
        g_Bb[idx] = c;
    }
}

// ---------------------------------------------------------------------------
// K2: fused per-edge temporal pipeline; conv2 & Wt1 via HMMA tf32.
// SMEM float offsets:
#define S_W2FH 0            // 12288: conv2 A-frags (hi)  [htile][kb24][lane][4]
#define S_W2FL 12288        // 12288: conv2 A-frags (lo)
#define S_WT1F 24576        // 4096 : Wt1 A-frags [htile][kb8][lane][4]
#define S_XSA  28672        // 11328: x1_hi -> x2 (f32)
#define S_XSB  40000        // 11328: x1_lo
#define S_ES   51328        // 160
#define S_ATT  51488        // 160
#define S_SPART 51648       // 640  : 4 htiles x 160
#define S_EFA  52288        // 512
#define S_SS   52800        // 16
#define S_TOTAL 52816       // floats -> 211264 B
// ---------------------------------------------------------------------------
extern __shared__ float smem[];

__global__ void __launch_bounds__(256, 1) k_edge(
    const float* __restrict__ ew,   const float* __restrict__ b1,
    const float* __restrict__ w2,   const float* __restrict__ b2,
    const float* __restrict__ Wt1,  const float* __restrict__ bt1,
    const float* __restrict__ Wt2,  const float* __restrict__ bt2,
    const float* __restrict__ Ws1,  const float* __restrict__ bs1,
    const float* __restrict__ Ws2,  const float* __restrict__ bs2)
{
    float* w2fh  = smem + S_W2FH;
    float* w2fl  = smem + S_W2FL;
    float* wt1f  = smem + S_WT1F;
    float* xs_a  = smem + S_XSA;
    float* xs_b  = smem + S_XSB;
    float* e_s   = smem + S_ES;
    float* att_s = smem + S_ATT;
    float* spart = smem + S_SPART;
    float* efa_s = smem + S_EFA;
    float* ss    = smem + S_SS;

    const int tid  = threadIdx.x;
    const int w    = tid >> 5;
    const int lane = tid & 31;
    const int htile = w & 3;       // 16 h-rows each
    const int nhalf = w >> 2;      // 80 n-cols each
    const int gid  = lane >> 2;    // 0..7
    const int tig  = lane & 3;     // 0..3

    // ---- one-time init: weight fragments -----------------------------------
    // conv2 A-frags: K ordering K = kk*64 + i
    for (int f = tid; f < 4 * 24 * 32; f += 256) {
        int ht = f / 768, rem = f % 768, kb = rem / 32, ln = rem % 32;
        int base_r = ht * 16 + (ln >> 2);
        int base_c = kb * 8 + (ln & 3);
        #pragma unroll
        for (int j = 0; j < 4; ++j) {
            int h = base_r + (j & 1) * 8;
            int kcol = base_c + (j >> 1) * 4;
            int kk = kcol >> 6, i = kcol & 63;
            float v = w2[(h * 64 + i) * 3 + kk];
            float hi = __uint_as_float(f2tf32(v));
            float lo = __uint_as_float(f2tf32(v - hi));
            w2fh[f * 4 + j] = hi;
            w2fl[f * 4 + j] = lo;
        }
    }
    // Wt1 A-frags: A[hout][hin] = Wt1[hin*64+hout]
    for (int f = tid; f < 4 * 8 * 32; f += 256) {
        int ht = f / 256, rem = f % 256, kb = rem / 32, ln = rem % 32;
        int base_r = ht * 16 + (ln >> 2);
        int base_c = kb * 8 + (ln & 3);
        #pragma unroll
        for (int j = 0; j < 4; ++j) {
            int h = base_r + (j & 1) * 8;
            int i = base_c + (j >> 1) * 4;
            wt1f[f * 4 + j] = __uint_as_float(f2tf32(Wt1[i * 64 + h]));
        }
    }
    // zero pads of both x tiles
    for (int f = tid; f < 64 * 2 * NE; f += 256) {
        int i = f / (2 * NE), p = f % (2 * NE);
        int e = p >> 1, side = p & 1;
        xs_a[i * XROW + e * ESLOT + side * 21] = 0.f;
        xs_b[i * XROW + e * ESLOT + side * 21] = 0.f;
    }
    __syncthreads();

    // ---- per-thread constant maps ------------------------------------------
    // B-gather columns: n = nhalf*80 + q*8 + gid
    int cq[10];
    #pragma unroll
    for (int q = 0; q < 10; ++q) {
        int n = nhalf * 80 + q * 8 + gid;
        cq[q] = (n / 20) * ESLOT + 1 + (n % 20);
    }
    // D columns: n0 = nhalf*80 + q*8 + tig*2
    int dq0[10], dq1[10];
    #pragma unroll
    for (int q = 0; q < 10; ++q) {
        int n0 = nhalf * 80 + q * 8 + tig * 2;
        dq0[q] = (n0 / 20) * ESLOT + 1 + (n0 % 20);
        int n1 = n0 + 1;
        dq1[q] = (n1 / 20) * ESLOT + 1 + (n1 % 20);
    }
    const int r0 = htile * 16 + gid;   // D rows r0, r0+8
    const float b2_0 = b2[r0],  b2_1 = b2[r0 + 8];
    const float bt1_0 = bt1[r0], bt1_1 = bt1[r0 + 8];
    const float wt2_0 = Wt2[r0], wt2_1 = Wt2[r0 + 8];
    const float bt2v = bt2[0];
    const float bs2v = bs2[0];

    // x1-stage constants: thread -> channel i, 2 edges
    const int xi = tid >> 2;           // channel 0..63
    const int xsub = tid & 3;          // edge pair selector
    float a1k[3], bbk[3];
    #pragma unroll
    for (int k = 0; k < 3; ++k) { a1k[k] = g_A1[xi * 3 + k]; bbk[k] = g_Bb[xi * 3 + k]; }
    const float b1v = b1[xi];
    const float c3  = b1v + bbk[0] + bbk[1] + bbk[2];
    const float c2a = b1v + bbk[1] + bbk[2];   // t = 0
    const float c2b = b1v + bbk[0] + bbk[1];   // t = 19

    for (int g = blockIdx.x; g < NGROUPS; g += gridDim.x) {
        const int m0 = g * NE;
        __syncthreads();  // SMEM reuse guard

        for (int f = tid; f < NE * TT; f += 256) e_s[f] = ew[m0 * TT + f];
        __syncthreads();

        // ---- x1 = relu(folded conv1), split hi/lo to tf32 -------------------
        #pragma unroll
        for (int ee = 0; ee < 2; ++ee) {
            const int e = xsub * 2 + ee;
            const float* ep = e_s + e * TT;
            float* oa = xs_a + xi * XROW + e * ESLOT + 1;
            float* ob = xs_b + xi * XROW + e * ESLOT + 1;
            #pragma unroll
            for (int t = 0; t < TT; ++t) {
                float x;
                if (t == 0)       x = c2a + a1k[1] * ep[0]  + a1k[2] * ep[1];
                else if (t == 19) x = c2b + a1k[0] * ep[18] + a1k[1] * ep[19];
                else x = c3 + a1k[0]*ep[t-1] + a1k[1]*ep[t] + a1k[2]*ep[t+1];
                x = fmaxf(x, 0.f);
                float hi = __uint_as_float(f2tf32(x));
                oa[t] = hi;
                ob[t] = __uint_as_float(f2tf32(x - hi));
            }
        }
        __syncthreads();

        // ---- conv2 via split-tf32 MMA: D[64 x 160], K = 192 ------------------
        float d[10][4];
        #pragma unroll
        for (int q = 0; q < 10; ++q)
            #pragma unroll
            for (int j = 0; j < 4; ++j) d[q][j] = 0.f;

        #pragma unroll 1
        for (int kb = 0; kb < 24; ++kb) {
            const int fo = ((htile * 24 + kb) * 32 + lane) * 4;
            const uint4 Ah = *(const uint4*)(w2fh + fo);
            const uint4 Al = *(const uint4*)(w2fl + fo);
            const int ib = (kb & 7) * 8 + tig;
            const int koff = (kb >> 3) - 1;
            const float* ba = xs_a + ib * XROW + koff;
            const float* bb = xs_b + ib * XROW + koff;
            #pragma unroll
            for (int q = 0; q < 10; ++q) {
                uint32_t bh0 = __float_as_uint(ba[cq[q]]);
                uint32_t bh1 = __float_as_uint(ba[cq[q] + 4 * XROW]);
                uint32_t bl0 = __float_as_uint(bb[cq[q]]);
                uint32_t bl1 = __float_as_uint(bb[cq[q] + 4 * XROW]);
                mma_tf32(d[q], Ah, bh0, bh1);
                mma_tf32(d[q], Al, bh0, bh1);
                mma_tf32(d[q], Ah, bl0, bl1);
            }
        }
        __syncthreads();  // all B reads done before overwriting xs_a

        // ---- epilogue: x2 = relu(d + b2) -> xs_a (full f32) ------------------
        #pragma unroll
        for (int q = 0; q < 10; ++q) {
            xs_a[ r0      * XROW + dq0[q]] = fmaxf(d[q][0] + b2_0, 0.f);
            xs_a[ r0      * XROW + dq1[q]] = fmaxf(d[q][1] + b2_0, 0.f);
            xs_a[(r0 + 8) * XROW + dq0[q]] = fmaxf(d[q][2] + b2_1, 0.f);
            xs_a[(r0 + 8) * XROW + dq1[q]] = fmaxf(d[q][3] + b2_1, 0.f);
        }
        __syncthreads();

        // ---- u_pre = Wt1^T @ x2 via tf32 MMA (damped path, raw trunc B) -----
        float d2[10][4];
        #pragma unroll
        for (int q = 0; q < 10; ++q)
            #pragma unroll
            for (int j = 0; j < 4; ++j) d2[q][j] = 0.f;

        #pragma unroll 1
        for (int kb = 0; kb < 8; ++kb) {
            const int fo = ((htile * 8 + kb) * 32 + lane) * 4;
            const uint4 A = *(const uint4*)(wt1f + fo);
            const int ib = kb * 8 + tig;
            const float* ba = xs_a + ib * XROW;
            #pragma unroll
            for (int q = 0; q < 10; ++q) {
                uint32_t b0 = __float_as_uint(ba[cq[q]]);
                uint32_t b1 = __float_as_uint(ba[cq[q] + 4 * XROW]);
                mma_tf32(d2[q], A, b0, b1);
            }
        }

        // ---- score partials: p[n] = sum_h tanh(u+bt1)*Wt2 --------------------
        #pragma unroll
        for (int q = 0; q < 10; ++q) {
            float s0 = tanha(d2[q][0] + bt1_0) * wt2_0
                     + tanha(d2[q][2] + bt1_1) * wt2_1;
            float s1 = tanha(d2[q][1] + bt1_0) * wt2_0
                     + tanha(d2[q][3] + bt1_1) * wt2_1;
            #pragma unroll
            for (int off = 4; off < 32; off <<= 1) {
                s0 += __shfl_xor_sync(0xffffffffu, s0, off);
                s1 += __shfl_xor_sync(0xffffffffu, s1, off);
            }
            if (lane < 4) {
                int n0 = nhalf * 80 + q * 8 + lane * 2;
                spart[htile * 160 + n0]     = s0;
                spart[htile * 160 + n0 + 1] = s1;
            }
        }
        __syncthreads();

        // ---- temporal softmax: warp w handles edge w -------------------------
        {
            float v = -1e30f;
            if (lane < TT) {
                int n = w * TT + lane;
                v = spart[n] + spart[160 + n] + spart[320 + n] + spart[480 + n]
                  + bt2v;
            }
            float mx = v;
            #pragma unroll
            for (int off = 16; off; off >>= 1)
                mx = fmaxf(mx, __shfl_xor_sync(0xffffffffu, mx, off));
            float ev = (lane < TT) ? expf(v - mx) : 0.f;
            float sum = ev;
            #pragma unroll
            for (int off = 16; off; off >>= 1)
                sum += __shfl_xor_sync(0xffffffffu, sum, off);
            if (lane < TT) att_s[w * TT + lane] = ev / sum;
        }
        __syncthreads();

        // ---- efa[e,h] = sum_t x2[h,t]*att[t] ---------------------------------
        for (int idx = tid; idx < NE * 64; idx += 256) {
            int e = idx >> 6, h = idx & 63;
            const float* xr = xs_a + h * XROW + e * ESLOT + 1;
            const float* at = att_s + e * TT;
            float a = 0.f;
            #pragma unroll
            for (int t = 0; t < TT; ++t) a += xr[t] * at[t];
            efa_s[idx] = a;
            g_efa[(m0 + e) * 64 + h] = a;
        }
        __syncthreads();

        // ---- spatial pre-attention score per edge ---------------------------
        #pragma unroll 1
        for (int it = 0; it < 2; ++it) {
            int idx = it * 256 + tid;
            int e = idx >> 6, h = idx & 63;
            const float* ef = efa_s + e * 64;
            float a0 = 0.f, a1 = 0.f;
            #pragma unroll 4
            for (int i = 0; i < 64; i += 2) {
                a0 += ef[i]     * Ws1[i * 64 + h];
                a1 += ef[i + 1] * Ws1[(i + 1) * 64 + h];
            }
            float val = tanha(a0 + a1 + bs1[h]) * Ws2[h];
            #pragma unroll
            for (int off = 16; off; off >>= 1)
                val += __shfl_xor_sync(0xffffffffu, val, off);
            if (lane == 0) ss[e * 2 + (w & 1)] = val;
            __syncthreads();
        }
        if (tid < NE) g_score[m0 + tid] = ss[tid * 2] + ss[tid * 2 + 1] + bs2v;
    }
}

// ---------------------------------------------------------------------------
// K3: per-batch spatial softmax over N*N = 10000 scores
// ---------------------------------------------------------------------------
__global__ void __launch_bounds__(1024) k_spatial() {
    __shared__ float red[1024];
    __shared__ float mx_s, z_s;
    int b = blockIdx.x, tid = threadIdx.x;
    const float* sc = g_score + b * (NN * NN);

    float mx = -1e30f;
    for (int i = tid; i < NN * NN; i += 1024) mx = fmaxf(mx, sc[i]);
    red[tid] = mx;
    __syncthreads();
    for (int s = 512; s; s >>= 1) {
        if (tid < s) red[tid] = fmaxf(red[tid], red[tid + s]);
        __syncthreads();
    }
    if (tid == 0) mx_s = red[0];
    __syncthreads();
    float m = mx_s, z = 0.f;
    for (int i = tid; i < NN * NN; i += 1024) z += expf(sc[i] - m);
    red[tid] = z;
    __syncthreads();
    for (int s = 512; s; s >>= 1) {
        if (tid < s) red[tid] += red[tid + s];
        __syncthreads();
    }
    if (tid == 0) z_s = red[0];
    __syncthreads();
    float inv = 1.f / z_s;
    for (int i = tid; i < NN * NN; i += 1024)
        g_attw[b * (NN * NN) + i] = expf(sc[i] - m) * inv;
}

// ---------------------------------------------------------------------------
// K4: node aggregation + 3-layer MLP. One block per (b,i) node.
// ---------------------------------------------------------------------------
__global__ void __launch_bounds__(128) k_node(
    const float* __restrict__ Wg1, const float* __restrict__ bg1,
    const float* __restrict__ Wg2, const float* __restrict__ bg2,
    const float* __restrict__ Wout, const float* __restrict__ bout,
    float* __restrict__ out)
{
    __shared__ float nsm[128], g1s[64], g2s[64];
    const int bi = blockIdx.x;
    const int tid = threadIdx.x;
    const int h = tid & 63, half = tid >> 6;

    const float* efa = g_efa + (size_t)bi * NN * HH;
    const float* aw  = g_attw + bi * NN;
    float a = 0.f;
    for (int j = half * 50; j < half * 50 + 50; ++j)
        a += efa[j * 64 + h] * aw[j];
    nsm[tid] = a;
    __syncthreads();
    if (tid < 64) nsm[tid] = nsm[tid] + nsm[tid + 64];
    __syncthreads();
    if (tid < 64) {
        float acc = bg1[tid];
        for (int i = 0; i < 64; ++i) acc += nsm[i] * Wg1[i * 64 + tid];
        g1s[tid] = fmaxf(acc, 0.f);
    }
    __syncthreads();
    if (tid < 64) {
        float acc = bg2[tid];
        for (int i = 0; i < 64; ++i) acc += g1s[i] * Wg2[i * 64 + tid];
        g2s[tid] = fmaxf(acc, 0.f);
    }
    __syncthreads();
    {
        float acc = bout[tid];
        for (int i = 0; i < 64; ++i) acc += g2s[i] * Wout[i * OO + tid];
        out[bi * OO + tid] = fmaxf(acc, 0.f);
    }
}

// ---------------------------------------------------------------------------
extern "C" void kernel_launch(void* const* d_in, const int* in_sizes, int n_in,
                              void* d_out, int out_size) {
    const float* ew   = (const float*)d_in[0];
    const float* We   = (const float*)d_in[1];
    const float* be   = (const float*)d_in[2];
    const float* w1   = (const float*)d_in[3];
    const float* b1   = (const float*)d_in[4];
    const float* w2   = (const float*)d_in[5];
    const float* b2   = (const float*)d_in[6];
    const float* Wt1  = (const float*)d_in[7];
    const float* bt1  = (const float*)d_in[8];
    const float* Wt2  = (const float*)d_in[9];
    const float* bt2  = (const float*)d_in[10];
    const float* Ws1  = (const float*)d_in[11];
    const float* bs1  = (const float*)d_in[12];
    const float* Ws2  = (const float*)d_in[13];
    const float* bs2  = (const float*)d_in[14];
    const float* Wg1  = (const float*)d_in[15];
    const float* bg1  = (const float*)d_in[16];
    const float* Wg2  = (const float*)d_in[17];
    const float* bg2  = (const float*)d_in[18];
    const float* Wout = (const float*)d_in[19];
    const float* bout = (const float*)d_in[20];
    float* out = (float*)d_out;

    const int smem_bytes = S_TOTAL * 4;  // 211264 B
    cudaFuncSetAttribute(k_edge, cudaFuncAttributeMaxDynamicSharedMemorySize,
                         smem_bytes);

    k_prep<<<1, 256>>>(w1, We, be);
    k_edge<<<148, 256, smem_bytes>>>(ew, b1, w2, b2, Wt1, bt1, Wt2, bt2,
                                     Ws1, bs1, Ws2, bs2);
    k_spatial<<<BB, 1024>>>();
    k_node<<<BB * NN, 128>>>(Wg1, bg1, Wg2, bg2, Wout, bout, out);
}

// round 4
// speedup vs baseline: 2.4353x; 1.5202x over previous
#include <cuda_runtime.h>
#include <math.h>
#include <stdint.h>

// Problem constants
#define BB 4
#define NN 100
#define TT 20
#define HH 64
#define OO 128
#define MM 40000          // B*N*N edges
#define NE 8              // edges per group
#define NGROUPS (MM/NE)   // 5000
#define ESLOT 22          // per-edge column slot: [0]=left pad, [1..20]=t, [21]=right pad
#define XROW (NE*ESLOT+1) // 177, odd stride for bank spread

// Scratch
__device__ float g_efa[MM * HH];   // 10.24 MB
__device__ float g_score[MM];
__device__ float g_attw[MM];
__device__ float g_A1[HH * 3];
__device__ float g_Bb[HH * 3];

// ---- helpers ---------------------------------------------------------------
__device__ __forceinline__ float tanha(float x) {
    float y;
    asm("tanh.approx.f32 %0, %1;" : "=f"(y) : "f"(x));
    return y;
}
__device__ __forceinline__ uint32_t f2tf32(float x) {
    uint32_t r;
    asm("cvt.rna.tf32.f32 %0, %1;" : "=r"(r) : "f"(x));
    return r;
}
// m16n8k8 tf32 MMA. A frag (a0..a3) = (r,c),(r+8,c),(r,c+4),(r+8,c+4);
// B frag b0=(k=lane%4, n=lane/4), b1=(k+4, n);
// D frag = (r,2c'),(r,2c'+1),(r+8,2c'),(r+8,2c'+1), r=lane/4, c'=lane%4.
__device__ __forceinline__ void mma_tf32(float d[4], uint4 a,
                                         uint32_t b0, uint32_t b1) {
    asm volatile(
        "mma.sync.aligned.m16n8k8.row.col.f32.tf32.tf32.f32 "
        "{%0,%1,%2,%3},{%4,%5,%6,%7},{%8,%9},{%0,%1,%2,%3};"
        : "+f"(d[0]), "+f"(d[1]), "+f"(d[2]), "+f"(d[3])
        : "r"(a.x), "r"(a.y), "r"(a.z), "r"(a.w), "r"(b0), "r"(b1));
}

// ---------------------------------------------------------------------------
// K0: fold conv1 weights against the rank-1 edge embedding
// ---------------------------------------------------------------------------
__global__ void k_prep(const float* __restrict__ w1,
                       const float* __restrict__ We,
                       const float* __restrict__ be) {
    int idx = threadIdx.x;
    if (idx < HH * 3) {
        int h = idx / 3, k = idx % 3;
        float a = 0.f, c = 0.f;
        for (int i = 0; i < HH; ++i) {
            float w = w1[(h * HH + i) * 3 + k];
            a += w * We[i];
            c += w * be[i];
        }
        g_A1[idx] = a;
        g_Bb[idx] = c;
    }
}

// ---------------------------------------------------------------------------
// K2: fused per-edge temporal pipeline; conv2 & Wt1 via HMMA tf32.
// conv2: 2-MMA scheme (weights split hi/lo, x single rna-tf32).
// SMEM float offsets:
#define S_W2FH 0            // 12288: conv2 A-frags (hi)  [htile][kb24][lane][4]
#define S_W2FL 12288        // 12288: conv2 A-frags (lo)
#define S_WT1F 24576        // 4096 : Wt1 A-frags [htile][kb8][lane][4]
#define S_WS1  28672        // 4096 : Ws1 [i][h]
#define S_XSA  32768        // 11328: x1 (rna-tf32) -> x2 (f32)
#define S_ES   44096        // 160
#define S_ATT  44256        // 160
#define S_SPART 44416       // 640  : 4 htiles x 160
#define S_EFA  45056        // 512
#define S_SS   45568        // 16
#define S_TOTAL 45584       // floats -> 182336 B
// ---------------------------------------------------------------------------
extern __shared__ float smem[];

__global__ void __launch_bounds__(256, 1) k_edge(
    const float* __restrict__ ew,   const float* __restrict__ b1,
    const float* __restrict__ w2,   const float* __restrict__ b2,
    const float* __restrict__ Wt1,  const float* __restrict__ bt1,
    const float* __restrict__ Wt2,  const float* __restrict__ bt2,
    const float* __restrict__ Ws1,  const float* __restrict__ bs1,
    const float* __restrict__ Ws2,  const float* __restrict__ bs2)
{
    float* w2fh  = smem + S_W2FH;
    float* w2fl  = smem + S_W2FL;
    float* wt1f  = smem + S_WT1F;
    float* ws1s  = smem + S_WS1;
    float* xs_a  = smem + S_XSA;
    float* e_s   = smem + S_ES;
    float* att_s = smem + S_ATT;
    float* spart = smem + S_SPART;
    float* efa_s = smem + S_EFA;
    float* ss    = smem + S_SS;

    const int tid  = threadIdx.x;
    const int w    = tid >> 5;
    const int lane = tid & 31;
    const int htile = w & 3;       // 16 h-rows each
    const int nhalf = w >> 2;      // 80 n-cols each
    const int gid  = lane >> 2;    // 0..7
    const int tig  = lane & 3;     // 0..3

    // ---- one-time init: weight fragments -----------------------------------
    for (int f = tid; f < 4 * 24 * 32; f += 256) {
        int ht = f / 768, rem = f % 768, kb = rem / 32, ln = rem % 32;
        int base_r = ht * 16 + (ln >> 2);
        int base_c = kb * 8 + (ln & 3);
        #pragma unroll
        for (int j = 0; j < 4; ++j) {
            int h = base_r + (j & 1) * 8;
            int kcol = base_c + (j >> 1) * 4;
            int kk = kcol >> 6, i = kcol & 63;
            float v = w2[(h * 64 + i) * 3 + kk];
            float hi = __uint_as_float(f2tf32(v));
            float lo = __uint_as_float(f2tf32(v - hi));
            w2fh[f * 4 + j] = hi;
            w2fl[f * 4 + j] = lo;
        }
    }
    for (int f = tid; f < 4 * 8 * 32; f += 256) {
        int ht = f / 256, rem = f % 256, kb = rem / 32, ln = rem % 32;
        int base_r = ht * 16 + (ln >> 2);
        int base_c = kb * 8 + (ln & 3);
        #pragma unroll
        for (int j = 0; j < 4; ++j) {
            int h = base_r + (j & 1) * 8;
            int i = base_c + (j >> 1) * 4;
            wt1f[f * 4 + j] = __uint_as_float(f2tf32(Wt1[i * 64 + h]));
        }
    }
    for (int f = tid; f < 4096; f += 256) ws1s[f] = Ws1[f];
    // zero pads of the x tile
    for (int f = tid; f < 64 * 2 * NE; f += 256) {
        int i = f / (2 * NE), p = f % (2 * NE);
        int e = p >> 1, side = p & 1;
        xs_a[i * XROW + e * ESLOT + side * 21] = 0.f;
    }

    // ---- per-thread constant maps ------------------------------------------
    int cq[10];
    #pragma unroll
    for (int q = 0; q < 10; ++q) {
        int n = nhalf * 80 + q * 8 + gid;
        cq[q] = (n / 20) * ESLOT + 1 + (n % 20);
    }
    int dq0[10], dq1[10];
    #pragma unroll
    for (int q = 0; q < 10; ++q) {
        int n0 = nhalf * 80 + q * 8 + tig * 2;
        dq0[q] = (n0 / 20) * ESLOT + 1 + (n0 % 20);
        int n1 = n0 + 1;
        dq1[q] = (n1 / 20) * ESLOT + 1 + (n1 % 20);
    }
    const int r0 = htile * 16 + gid;   // D rows r0, r0+8
    const float b2_0 = b2[r0],  b2_1 = b2[r0 + 8];
    const float bt1_0 = bt1[r0], bt1_1 = bt1[r0 + 8];
    const float wt2_0 = Wt2[r0], wt2_1 = Wt2[r0 + 8];
    const float bt2v = bt2[0];
    const float bs2v = bs2[0];

    // x1-stage constants: thread -> channel i, 2 edges
    const int xi = tid >> 2;           // channel 0..63
    const int xsub = tid & 3;          // edge pair selector
    float a1k[3], bbk[3];
    #pragma unroll
    for (int k = 0; k < 3; ++k) { a1k[k] = g_A1[xi * 3 + k]; bbk[k] = g_Bb[xi * 3 + k]; }
    const float b1v = b1[xi];
    const float c3  = b1v + bbk[0] + bbk[1] + bbk[2];
    const float c2a = b1v + bbk[1] + bbk[2];   // t = 0
    const float c2b = b1v + bbk[0] + bbk[1];   // t = 19

    // prefetch first group's edge scalars
    float epref = 0.f;
    if (blockIdx.x < NGROUPS && tid < NE * TT)
        epref = ew[blockIdx.x * (NE * TT) + tid];

    for (int g = blockIdx.x; g < NGROUPS; g += gridDim.x) {
        const int m0 = g * NE;

        // stash prefetched scalars; issue next group's prefetch
        if (tid < NE * TT) e_s[tid] = epref;
        const int gn = g + gridDim.x;
        if (gn < NGROUPS && tid < NE * TT)
            epref = ew[gn * (NE * TT) + tid];
        __syncthreads();   // e_s visible; prior-group xs_a reads long done

        // ---- x1 = relu(folded conv1), single rna-tf32 ------------------------
        #pragma unroll
        for (int ee = 0; ee < 2; ++ee) {
            const int e = xsub * 2 + ee;
            const float* ep = e_s + e * TT;
            float* oa = xs_a + xi * XROW + e * ESLOT + 1;
            #pragma unroll
            for (int t = 0; t < TT; ++t) {
                float x;
                if (t == 0)       x = c2a + a1k[1] * ep[0]  + a1k[2] * ep[1];
                else if (t == 19) x = c2b + a1k[0] * ep[18] + a1k[1] * ep[19];
                else x = c3 + a1k[0]*ep[t-1] + a1k[1]*ep[t] + a1k[2]*ep[t+1];
                x = fmaxf(x, 0.f);
                oa[t] = __uint_as_float(f2tf32(x));
            }
        }
        __syncthreads();

        // ---- conv2 via 2-MMA split: D[64 x 160], K = 192 ---------------------
        float d[10][4];
        #pragma unroll
        for (int q = 0; q < 10; ++q)
            #pragma unroll
            for (int j = 0; j < 4; ++j) d[q][j] = 0.f;

        #pragma unroll 1
        for (int kb = 0; kb < 24; ++kb) {
            const int fo = ((htile * 24 + kb) * 32 + lane) * 4;
            const uint4 Ah = *(const uint4*)(w2fh + fo);
            const uint4 Al = *(const uint4*)(w2fl + fo);
            const int ib = (kb & 7) * 8 + tig;
            const int koff = (kb >> 3) - 1;
            const float* ba = xs_a + ib * XROW + koff;
            #pragma unroll
            for (int q = 0; q < 10; ++q) {
                uint32_t bh0 = __float_as_uint(ba[cq[q]]);
                uint32_t bh1 = __float_as_uint(ba[cq[q] + 4 * XROW]);
                mma_tf32(d[q], Ah, bh0, bh1);
                mma_tf32(d[q], Al, bh0, bh1);
            }
        }
        __syncthreads();  // all B reads done before overwriting xs_a

        // ---- epilogue: x2 = relu(d + b2) -> xs_a (full f32) ------------------
        #pragma unroll
        for (int q = 0; q < 10; ++q) {
            xs_a[ r0      * XROW + dq0[q]] = fmaxf(d[q][0] + b2_0, 0.f);
            xs_a[ r0      * XROW + dq1[q]] = fmaxf(d[q][1] + b2_0, 0.f);
            xs_a[(r0 + 8) * XROW + dq0[q]] = fmaxf(d[q][2] + b2_1, 0.f);
            xs_a[(r0 + 8) * XROW + dq1[q]] = fmaxf(d[q][3] + b2_1, 0.f);
        }
        __syncthreads();

        // ---- u_pre = Wt1^T @ x2 via tf32 MMA (damped path, raw trunc B) -----
        float d2[10][4];
        #pragma unroll
        for (int q = 0; q < 10; ++q)
            #pragma unroll
            for (int j = 0; j < 4; ++j) d2[q][j] = 0.f;

        #pragma unroll 1
        for (int kb = 0; kb < 8; ++kb) {
            const int fo = ((htile * 8 + kb) * 32 + lane) * 4;
            const uint4 A = *(const uint4*)(wt1f + fo);
            const int ib = kb * 8 + tig;
            const float* ba = xs_a + ib * XROW;
            #pragma unroll
            for (int q = 0; q < 10; ++q) {
                uint32_t b0 = __float_as_uint(ba[cq[q]]);
                uint32_t b1 = __float_as_uint(ba[cq[q] + 4 * XROW]);
                mma_tf32(d2[q], A, b0, b1);
            }
        }

        // ---- score partials: p[n] = sum_h tanh(u+bt1)*Wt2 --------------------
        #pragma unroll
        for (int q = 0; q < 10; ++q) {
            float s0 = tanha(d2[q][0] + bt1_0) * wt2_0
                     + tanha(d2[q][2] + bt1_1) * wt2_1;
            float s1 = tanha(d2[q][1] + bt1_0) * wt2_0
                     + tanha(d2[q][3] + bt1_1) * wt2_1;
            #pragma unroll
            for (int off = 4; off < 32; off <<= 1) {
                s0 += __shfl_xor_sync(0xffffffffu, s0, off);
                s1 += __shfl_xor_sync(0xffffffffu, s1, off);
            }
            if (lane < 4) {
                int n0 = nhalf * 80 + q * 8 + lane * 2;
                spart[htile * 160 + n0]     = s0;
                spart[htile * 160 + n0 + 1] = s1;
            }
        }
        __syncthreads();

        // ---- temporal softmax: warp w handles edge w -------------------------
        {
            float v = -1e30f;
            if (lane < TT) {
                int n = w * TT + lane;
                v = spart[n] + spart[160 + n] + spart[320 + n] + spart[480 + n]
                  + bt2v;
            }
            float mx = v;
            #pragma unroll
            for (int off = 16; off; off >>= 1)
                mx = fmaxf(mx, __shfl_xor_sync(0xffffffffu, mx, off));
            float ev = (lane < TT) ? expf(v - mx) : 0.f;
            float sum = ev;
            #pragma unroll
            for (int off = 16; off; off >>= 1)
                sum += __shfl_xor_sync(0xffffffffu, sum, off);
            if (lane < TT) att_s[w * TT + lane] = ev / sum;
        }
        __syncthreads();

        // ---- efa[e,h] = sum_t x2[h,t]*att[t] ---------------------------------
        for (int idx = tid; idx < NE * 64; idx += 256) {
            int e = idx >> 6, h = idx & 63;
            const float* xr = xs_a + h * XROW + e * ESLOT + 1;
            const float* at = att_s + e * TT;
            float a = 0.f;
            #pragma unroll
            for (int t = 0; t < TT; ++t) a += xr[t] * at[t];
            efa_s[idx] = a;
            g_efa[(m0 + e) * 64 + h] = a;
        }
        __syncthreads();

        // ---- spatial pre-attention score per edge ---------------------------
        #pragma unroll 1
        for (int it = 0; it < 2; ++it) {
            int idx = it * 256 + tid;
            int e = idx >> 6, h = idx & 63;
            const float* ef = efa_s + e * 64;
            float a0 = 0.f, a1 = 0.f;
            #pragma unroll 8
            for (int i = 0; i < 64; i += 2) {
                a0 += ef[i]     * ws1s[i * 64 + h];
                a1 += ef[i + 1] * ws1s[(i + 1) * 64 + h];
            }
            float val = tanha(a0 + a1 + bs1[h]) * Ws2[h];
            #pragma unroll
            for (int off = 16; off; off >>= 1)
                val += __shfl_xor_sync(0xffffffffu, val, off);
            if (lane == 0) ss[e * 2 + (w & 1)] = val;
            __syncthreads();
        }
        if (tid < NE) g_score[m0 + tid] = ss[tid * 2] + ss[tid * 2 + 1] + bs2v;
    }
}

// ---------------------------------------------------------------------------
// K3: per-batch spatial softmax over N*N = 10000 scores
// ---------------------------------------------------------------------------
__global__ void __launch_bounds__(1024) k_spatial() {
    __shared__ float red[1024];
    __shared__ float mx_s, z_s;
    int b = blockIdx.x, tid = threadIdx.x;
    const float* sc = g_score + b * (NN * NN);

    float mx = -1e30f;
    for (int i = tid; i < NN * NN; i += 1024) mx = fmaxf(mx, sc[i]);
    red[tid] = mx;
    __syncthreads();
    for (int s = 512; s; s >>= 1) {
        if (tid < s) red[tid] = fmaxf(red[tid], red[tid + s]);
        __syncthreads();
    }
    if (tid == 0) mx_s = red[0];
    __syncthreads();
    float m = mx_s, z = 0.f;
    for (int i = tid; i < NN * NN; i += 1024) z += expf(sc[i] - m);
    red[tid] = z;
    __syncthreads();
    for (int s = 512; s; s >>= 1) {
        if (tid < s) red[tid] += red[tid + s];
        __syncthreads();
    }
    if (tid == 0) z_s = red[0];
    __syncthreads();
    float inv = 1.f / z_s;
    for (int i = tid; i < NN * NN; i += 1024)
        g_attw[b * (NN * NN) + i] = expf(sc[i] - m) * inv;
}

// ---------------------------------------------------------------------------
// K4: node aggregation + 3-layer MLP. One block per (b,i) node.
// ---------------------------------------------------------------------------
__global__ void __launch_bounds__(128) k_node(
    const float* __restrict__ Wg1, const float* __restrict__ bg1,
    const float* __restrict__ Wg2, const float* __restrict__ bg2,
    const float* __restrict__ Wout, const float* __restrict__ bout,
    float* __restrict__ out)
{
    __shared__ float nsm[128], g1s[64], g2s[64];
    const int bi = blockIdx.x;
    const int tid = threadIdx.x;
    const int h = tid & 63, half = tid >> 6;

    const float* efa = g_efa + (size_t)bi * NN * HH;
    const float* aw  = g_attw + bi * NN;
    float a = 0.f;
    for (int j = half * 50; j < half * 50 + 50; ++j)
        a += efa[j * 64 + h] * aw[j];
    nsm[tid] = a;
    __syncthreads();
    if (tid < 64) nsm[tid] = nsm[tid] + nsm[tid + 64];
    __syncthreads();
    if (tid < 64) {
        float acc = bg1[tid];
        for (int i = 0; i < 64; ++i) acc += nsm[i] * Wg1[i * 64 + tid];
        g1s[tid] = fmaxf(acc, 0.f);
    }
    __syncthreads();
    if (tid < 64) {
        float acc = bg2[tid];
        for (int i = 0; i < 64; ++i) acc += g1s[i] * Wg2[i * 64 + tid];
        g2s[tid] = fmaxf(acc, 0.f);
    }
    __syncthreads();
    {
        float acc = bout[tid];
        for (int i = 0; i < 64; ++i) acc += g2s[i] * Wout[i * OO + tid];
        out[bi * OO + tid] = fmaxf(acc, 0.f);
    }
}

// ---------------------------------------------------------------------------
extern "C" void kernel_launch(void* const* d_in, const int* in_sizes, int n_in,
                              void* d_out, int out_size) {
    const float* ew   = (const float*)d_in[0];
    const float* We   = (const float*)d_in[1];
    const float* be   = (const float*)d_in[2];
    const float* w1   = (const float*)d_in[3];
    const float* b1   = (const float*)d_in[4];
    const float* w2   = (const float*)d_in[5];
    const float* b2   = (const float*)d_in[6];
    const float* Wt1  = (const float*)d_in[7];
    const float* bt1  = (const float*)d_in[8];
    const float* Wt2  = (const float*)d_in[9];
    const float* bt2  = (const float*)d_in[10];
    const float* Ws1  = (const float*)d_in[11];
    const float* bs1  = (const float*)d_in[12];
    const float* Ws2  = (const float*)d_in[13];
    const float* bs2  = (const float*)d_in[14];
    const float* Wg1  = (const float*)d_in[15];
    const float* bg1  = (const float*)d_in[16];
    const float* Wg2  = (const float*)d_in[17];
    const float* bg2  = (const float*)d_in[18];
    const float* Wout = (const float*)d_in[19];
    const float* bout = (const float*)d_in[20];
    float* out = (float*)d_out;

    const int smem_bytes = S_TOTAL * 4;  // 182336 B
    cudaFuncSetAttribute(k_edge, cudaFuncAttributeMaxDynamicSharedMemorySize,
                         smem_bytes);

    k_prep<<<1, 256>>>(w1, We, be);
    k_edge<<<148, 256, smem_bytes>>>(ew, b1, w2, b2, Wt1, bt1, Wt2, bt2,
                                     Ws1, bs1, Ws2, bs2);
    k_spatial<<<BB, 1024>>>();
    k_node<<<BB * NN, 128>>>(Wg1, bg1, Wg2, bg2, Wout, bout, out);
}

// round 5
// speedup vs baseline: 2.6667x; 1.0950x over previous
#include <cuda_runtime.h>
#include <cuda_bf16.h>
#include <math.h>
#include <stdint.h>

// Problem constants
#define BB 4
#define NN 100
#define TT 20
#define HH 64
#define OO 128
#define MM 40000            // B*N*N edges
#define NE 16               // edges per group
#define NGROUPS (MM/NE)     // 2500
#define ESLOT 22            // [0]=left pad, [1..20]=t, [21]=right pad
#define XROW2 (NE*ESLOT+1)  // 353 words/row, odd for bank spread
#define NTHREADS 512

// Scratch
__device__ float g_efa[MM * HH];   // 10.24 MB
__device__ float g_score[MM];
__device__ float g_attw[MM];
__device__ float g_A1[HH * 3];
__device__ float g_Bb[HH * 3];

// ---- helpers ---------------------------------------------------------------
__device__ __forceinline__ float tanha(float x) {
    float y;
    asm("tanh.approx.f32 %0, %1;" : "=f"(y) : "f"(x));
    return y;
}
__device__ __forceinline__ uint32_t f2tf32(float x) {
    uint32_t r;
    asm("cvt.rna.tf32.f32 %0, %1;" : "=r"(r) : "f"(x));
    return r;
}
// pack two f32 -> bf16x2 word; 'lo' lands in low 16 bits (first k element)
__device__ __forceinline__ uint32_t pkbf2(float lo, float hi) {
    uint32_t r;
    asm("cvt.rn.bf16x2.f32 %0, %1, %2;" : "=r"(r) : "f"(hi), "f"(lo));
    return r;
}
__device__ __forceinline__ float bf16f(float v) {
    return __bfloat162float(__float2bfloat16(v));
}
// m16n8k16 bf16 MMA. A(16x16) row-major frag a0..a3 (each 2 bf16 along k):
//  a0=(r,k0..k0+1) a1=(r+8,k0..) a2=(r,k0+8..) a3=(r+8,k0+8..), r=lane/4,k0=(lane%4)*2
// B(16x8) col-major: b0=(k0..k0+1, n=lane/4), b1=(k0+8.., n)
// D: d0,d1=(r,2c),(r,2c+1); d2,d3=(r+8,..), c=lane%4
__device__ __forceinline__ void mma_bf16(float d[4], uint4 a,
                                         uint32_t b0, uint32_t b1) {
    asm volatile(
        "mma.sync.aligned.m16n8k16.row.col.f32.bf16.bf16.f32 "
        "{%0,%1,%2,%3},{%4,%5,%6,%7},{%8,%9},{%0,%1,%2,%3};"
        : "+f"(d[0]), "+f"(d[1]), "+f"(d[2]), "+f"(d[3])
        : "r"(a.x), "r"(a.y), "r"(a.z), "r"(a.w), "r"(b0), "r"(b1));
}
// m16n8k8 tf32 MMA (Wt1 path)
__device__ __forceinline__ void mma_tf32(float d[4], uint4 a,
                                         uint32_t b0, uint32_t b1) {
    asm volatile(
        "mma.sync.aligned.m16n8k8.row.col.f32.tf32.tf32.f32 "
        "{%0,%1,%2,%3},{%4,%5,%6,%7},{%8,%9},{%0,%1,%2,%3};"
        : "+f"(d[0]), "+f"(d[1]), "+f"(d[2]), "+f"(d[3])
        : "r"(a.x), "r"(a.y), "r"(a.z), "r"(a.w), "r"(b0), "r"(b1));
}

// ---------------------------------------------------------------------------
// K0: fold conv1 weights against the rank-1 edge embedding
// ---------------------------------------------------------------------------
__global__ void k_prep(const float* __restrict__ w1,
                       const float* __restrict__ We,
                       const float* __restrict__ be) {
    int idx = threadIdx.x;
    if (idx < HH * 3) {
        int h = idx / 3, k = idx % 3;
        float a = 0.f, c = 0.f;
        for (int i = 0; i < HH; ++i) {
            float w = w1[(h * HH + i) * 3 + k];
            a += w * We[i];
            c += w * be[i];
        }
        g_A1[idx] = a;
        g_Bb[idx] = c;
    }
}

// ---------------------------------------------------------------------------
// K2: fused per-edge temporal pipeline; conv2 bf16 HMMA (split weights),
// Wt1 tf32 HMMA. 512 threads, 16 edges/group.
// SMEM word offsets:
#define S_W2FH 0            // 6144 : conv2 A-frags hi (bf16x2) [ht][kb12][lane][4]
#define S_W2FL 6144         // 6144 : conv2 A-frags lo
#define S_WT1F 12288        // 4096 : Wt1 A-frags (tf32) [ht][kb8][lane][4]
#define S_WS1  16384        // 4096 : Ws1 [i][h]
#define S_XS   20480        // 22592: x1 packed bf16x2 (rows 0..31) -> x2 f32 (rows 0..63)
#define S_ES   43072        // 320
#define S_ATT  43392        // 320
#define S_SPART 43712       // 1280 : 4 htiles x 320
#define S_EFA  44992        // 1024
#define S_SS   46016        // 32
#define S_TOTAL 46048       // words -> 184192 B
// ---------------------------------------------------------------------------
extern __shared__ float smem[];

__global__ void __launch_bounds__(NTHREADS, 1) k_edge(
    const float* __restrict__ ew,   const float* __restrict__ b1,
    const float* __restrict__ w2,   const float* __restrict__ b2,
    const float* __restrict__ Wt1,  const float* __restrict__ bt1,
    const float* __restrict__ Wt2,  const float* __restrict__ bt2,
    const float* __restrict__ Ws1,  const float* __restrict__ bs1,
    const float* __restrict__ Ws2,  const float* __restrict__ bs2)
{
    uint32_t* w2fh = (uint32_t*)(smem + S_W2FH);
    uint32_t* w2fl = (uint32_t*)(smem + S_W2FL);
    float* wt1f  = smem + S_WT1F;
    float* ws1s  = smem + S_WS1;
    float* xs    = smem + S_XS;
    uint32_t* xsu = (uint32_t*)xs;
    float* e_s   = smem + S_ES;
    float* att_s = smem + S_ATT;
    float* spart = smem + S_SPART;
    float* efa_s = smem + S_EFA;
    float* ss    = smem + S_SS;

    const int tid  = threadIdx.x;
    const int w    = tid >> 5;
    const int lane = tid & 31;
    const int htile = w & 3;       // 16 h-rows each
    const int nhalf = w >> 2;      // 0..3, 80 n-cols each
    const int gid  = lane >> 2;    // 0..7
    const int tig  = lane & 3;     // 0..3

    // ---- one-time init: conv2 bf16 A-frags (hi/lo split) -------------------
    for (int f = tid; f < 4 * 12 * 32; f += NTHREADS) {
        int ht = f / 384, rem = f % 384, kb = rem / 32, ln = rem % 32;
        int r = ht * 16 + (ln >> 2);
        int k0 = (ln & 3) * 2;
        int kk = kb >> 2, ibase = (kb & 3) * 16;
        #pragma unroll
        for (int j = 0; j < 4; ++j) {
            int h  = r + (j & 1) * 8;
            int kl = k0 + (j >> 1) * 8;
            float v0 = w2[(h * 64 + ibase + kl) * 3 + kk];
            float v1 = w2[(h * 64 + ibase + kl + 1) * 3 + kk];
            float h0 = bf16f(v0), h1 = bf16f(v1);
            w2fh[f * 4 + j] = pkbf2(v0, v1);
            w2fl[f * 4 + j] = pkbf2(v0 - h0, v1 - h1);
        }
    }
    // Wt1 tf32 A-frags: A[hout][hin] = Wt1[hin*64+hout]
    for (int f = tid; f < 4 * 8 * 32; f += NTHREADS) {
        int ht = f / 256, rem = f % 256, kb = rem / 32, ln = rem % 32;
        int base_r = ht * 16 + (ln >> 2);
        int base_c = kb * 8 + (ln & 3);
        #pragma unroll
        for (int j = 0; j < 4; ++j) {
            int h = base_r + (j & 1) * 8;
            int i = base_c + (j >> 1) * 4;
            wt1f[f * 4 + j] = __uint_as_float(f2tf32(Wt1[i * 64 + h]));
        }
    }
    for (int f = tid; f < 4096; f += NTHREADS) ws1s[f] = Ws1[f];
    // zero the pad words of the packed x1 rows (0..31), never overwritten by x1
    for (int f = tid; f < 32 * 2 * NE; f += NTHREADS) {
        int pr = f / (2 * NE), p = f % (2 * NE);
        int e = p >> 1, side = p & 1;
        xsu[pr * XROW2 + e * ESLOT + side * 21] = 0u;
    }

    // ---- per-thread constant maps -------------------------------------------
    int cq[10];
    #pragma unroll
    for (int q = 0; q < 10; ++q) {
        int n = nhalf * 80 + q * 8 + gid;
        cq[q] = (n / 20) * ESLOT + 1 + (n % 20);
    }
    const int r0 = htile * 16 + gid;   // D rows r0, r0+8
    const float b2_0 = b2[r0],  b2_1 = b2[r0 + 8];
    const float bt1_0 = bt1[r0], bt1_1 = bt1[r0 + 8];
    const float wt2_0 = Wt2[r0], wt2_1 = Wt2[r0 + 8];
    const float bt2v = bt2[0];
    const float bs2v = bs2[0];

    // x1-stage mapping: thread -> channel pair (2pr, 2pr+1), one edge
    const int pr = tid >> 4;           // 0..31
    const int xe = tid & 15;           // edge 0..15
    const int c0 = pr * 2, c1 = c0 + 1;
    float a1k0[3], a1k1[3];
    float s0c = 0.f, s1c = 0.f;
    #pragma unroll
    for (int k = 0; k < 3; ++k) {
        a1k0[k] = g_A1[c0 * 3 + k];  a1k1[k] = g_A1[c1 * 3 + k];
        s0c += g_Bb[c0 * 3 + k];     s1c += g_Bb[c1 * 3 + k];
    }
    const float b1v0 = b1[c0], b1v1 = b1[c1];
    const float c3_0 = b1v0 + s0c;                      // interior t
    const float c3_1 = b1v1 + s1c;
    const float ca_0 = c3_0 - g_Bb[c0 * 3 + 0];         // t = 0 (no k=0 tap)
    const float ca_1 = c3_1 - g_Bb[c1 * 3 + 0];
    const float cb_0 = c3_0 - g_Bb[c0 * 3 + 2];         // t = 19 (no k=2 tap)
    const float cb_1 = c3_1 - g_Bb[c1 * 3 + 2];

    // prefetch first group's edge scalars
    float epref = 0.f;
    if (blockIdx.x < NGROUPS && tid < NE * TT)
        epref = ew[blockIdx.x * (NE * TT) + tid];

    for (int g = blockIdx.x; g < NGROUPS; g += gridDim.x) {
        const int m0 = g * NE;

        if (tid < NE * TT) e_s[tid] = epref;
        const int gn = g + gridDim.x;
        if (gn < NGROUPS && tid < NE * TT)
            epref = ew[gn * (NE * TT) + tid];
        __syncthreads();

        // ---- x1 = relu(folded conv1), packed bf16x2 by channel pair ----------
        {
            const float* ep = e_s + xe * TT;
            uint32_t* oa = xsu + pr * XROW2 + xe * ESLOT + 1;
            #pragma unroll
            for (int t = 0; t < TT; ++t) {
                float x0, x1v;
                if (t == 0) {
                    x0 = ca_0 + a1k0[1] * ep[0] + a1k0[2] * ep[1];
                    x1v = ca_1 + a1k1[1] * ep[0] + a1k1[2] * ep[1];
                } else if (t == 19) {
                    x0 = cb_0 + a1k0[0] * ep[18] + a1k0[1] * ep[19];
                    x1v = cb_1 + a1k1[0] * ep[18] + a1k1[1] * ep[19];
                } else {
                    x0 = c3_0 + a1k0[0]*ep[t-1] + a1k0[1]*ep[t] + a1k0[2]*ep[t+1];
                    x1v = c3_1 + a1k1[0]*ep[t-1] + a1k1[1]*ep[t] + a1k1[2]*ep[t+1];
                }
                oa[t] = pkbf2(fmaxf(x0, 0.f), fmaxf(x1v, 0.f));
            }
        }
        __syncthreads();

        // ---- conv2 via bf16 MMA (weights hi/lo): D[64 x 320], K = 192 --------
        float d[10][4];
        #pragma unroll
        for (int q = 0; q < 10; ++q)
            #pragma unroll
            for (int j = 0; j < 4; ++j) d[q][j] = 0.f;

        #pragma unroll 1
        for (int kb = 0; kb < 12; ++kb) {
            const int fo = ((htile * 12 + kb) * 32 + lane) * 4;
            const uint4 Ah = *(const uint4*)(w2fh + fo);
            const uint4 Al = *(const uint4*)(w2fl + fo);
            const int prow = (kb & 3) * 8 + tig;       // pair-row for b0
            const int koff = (kb >> 2) - 1;
            const uint32_t* bp = xsu + prow * XROW2 + koff;
            #pragma unroll
            for (int q = 0; q < 10; ++q) {
                uint32_t b0 = bp[cq[q]];
                uint32_t b1 = bp[cq[q] + 4 * XROW2];
                mma_bf16(d[q], Ah, b0, b1);
                mma_bf16(d[q], Al, b0, b1);
            }
        }
        __syncthreads();  // all B reads done before overwriting xs

        // ---- epilogue: x2 = relu(d + b2) -> xs (full f32) ---------------------
        #pragma unroll
        for (int q = 0; q < 10; ++q) {
            int n0 = nhalf * 80 + q * 8 + tig * 2;
            int col0 = (n0 / 20) * ESLOT + 1 + (n0 % 20);
            int n1 = n0 + 1;
            int col1 = (n1 / 20) * ESLOT + 1 + (n1 % 20);
            xs[ r0      * XROW2 + col0] = fmaxf(d[q][0] + b2_0, 0.f);
            xs[ r0      * XROW2 + col1] = fmaxf(d[q][1] + b2_0, 0.f);
            xs[(r0 + 8) * XROW2 + col0] = fmaxf(d[q][2] + b2_1, 0.f);
            xs[(r0 + 8) * XROW2 + col1] = fmaxf(d[q][3] + b2_1, 0.f);
        }
        __syncthreads();

        // ---- u_pre = Wt1^T @ x2 via tf32 MMA (raw-trunc B) --------------------
        float d2[10][4];
        #pragma unroll
        for (int q = 0; q < 10; ++q)
            #pragma unroll
            for (int j = 0; j < 4; ++j) d2[q][j] = 0.f;

        #pragma unroll 1
        for (int kb = 0; kb < 8; ++kb) {
            const int fo = ((htile * 8 + kb) * 32 + lane) * 4;
            const uint4 A = *(const uint4*)(wt1f + fo);
            const int ib = kb * 8 + tig;
            const float* ba = xs + ib * XROW2;
            #pragma unroll
            for (int q = 0; q < 10; ++q) {
                uint32_t b0 = __float_as_uint(ba[cq[q]]);
                uint32_t b1 = __float_as_uint(ba[cq[q] + 4 * XROW2]);
                mma_tf32(d2[q], A, b0, b1);
            }
        }

        // ---- score partials: p[n] = sum_h tanh(u+bt1)*Wt2 ---------------------
        #pragma unroll
        for (int q = 0; q < 10; ++q) {
            float s0 = tanha(d2[q][0] + bt1_0) * wt2_0
                     + tanha(d2[q][2] + bt1_1) * wt2_1;
            float s1 = tanha(d2[q][1] + bt1_0) * wt2_0
                     + tanha(d2[q][3] + bt1_1) * wt2_1;
            #pragma unroll
            for (int off = 4; off < 32; off <<= 1) {
                s0 += __shfl_xor_sync(0xffffffffu, s0, off);
                s1 += __shfl_xor_sync(0xffffffffu, s1, off);
            }
            if (lane < 4) {
                int n0 = nhalf * 80 + q * 8 + lane * 2;
                spart[htile * 320 + n0]     = s0;
                spart[htile * 320 + n0 + 1] = s1;
            }
        }
        __syncthreads();

        // ---- temporal softmax: warp w handles edge w --------------------------
        {
            float v = -1e30f;
            if (lane < TT) {
                int n = w * TT + lane;
                v = spart[n] + spart[320 + n] + spart[640 + n] + spart[960 + n]
                  + bt2v;
            }
            float mx = v;
            #pragma unroll
            for (int off = 16; off; off >>= 1)
                mx = fmaxf(mx, __shfl_xor_sync(0xffffffffu, mx, off));
            float ev = (lane < TT) ? expf(v - mx) : 0.f;
            float sum = ev;
            #pragma unroll
            for (int off = 16; off; off >>= 1)
                sum += __shfl_xor_sync(0xffffffffu, sum, off);
            if (lane < TT) att_s[w * TT + lane] = ev / sum;
        }
        __syncthreads();

        // ---- efa[e,h] = sum_t x2[h,t]*att[t] ----------------------------------
        for (int idx = tid; idx < NE * 64; idx += NTHREADS) {
            int e = idx >> 6, h = idx & 63;
            const float* xr = xs + h * XROW2 + e * ESLOT + 1;
            const float* at = att_s + e * TT;
            float a = 0.f;
            #pragma unroll
            for (int t = 0; t < TT; ++t) a += xr[t] * at[t];
            efa_s[idx] = a;
            g_efa[(m0 + e) * 64 + h] = a;
        }
        __syncthreads();

        // ---- spatial pre-attention score per edge -----------------------------
        #pragma unroll 1
        for (int it = 0; it < 2; ++it) {
            int idx = it * NTHREADS + tid;
            int e = idx >> 6, h = idx & 63;
            int half = (idx >> 5) & 1;
            const float* ef = efa_s + e * 64;
            float a0 = 0.f, a1 = 0.f;
            #pragma unroll 8
            for (int i = 0; i < 64; i += 2) {
                a0 += ef[i]     * ws1s[i * 64 + h];
                a1 += ef[i + 1] * ws1s[(i + 1) * 64 + h];
            }
            float val = tanha(a0 + a1 + bs1[h]) * Ws2[h];
            #pragma unroll
            for (int off = 16; off; off >>= 1)
                val += __shfl_xor_sync(0xffffffffu, val, off);
            if (lane == 0) ss[e * 2 + half] = val;
        }
        __syncthreads();
        if (tid < NE) g_score[m0 + tid] = ss[tid * 2] + ss[tid * 2 + 1] + bs2v;
    }
}

// ---------------------------------------------------------------------------
// K3: per-batch spatial softmax over N*N = 10000 scores
// ---------------------------------------------------------------------------
__global__ void __launch_bounds__(1024) k_spatial() {
    __shared__ float red[1024];
    __shared__ float mx_s, z_s;
    int b = blockIdx.x, tid = threadIdx.x;
    const float* sc = g_score + b * (NN * NN);

    float mx = -1e30f;
    for (int i = tid; i < NN * NN; i += 1024) mx = fmaxf(mx, sc[i]);
    red[tid] = mx;
    __syncthreads();
    for (int s = 512; s; s >>= 1) {
        if (tid < s) red[tid] = fmaxf(red[tid], red[tid + s]);
        __syncthreads();
    }
    if (tid == 0) mx_s = red[0];
    __syncthreads();
    float m = mx_s, z = 0.f;
    for (int i = tid; i < NN * NN; i += 1024) z += expf(sc[i] - m);
    red[tid] = z;
    __syncthreads();
    for (int s = 512; s; s >>= 1) {
        if (tid < s) red[tid] += red[tid + s];
        __syncthreads();
    }
    if (tid == 0) z_s = red[0];
    __syncthreads();
    float inv = 1.f / z_s;
    for (int i = tid; i < NN * NN; i += 1024)
        g_attw[b * (NN * NN) + i] = expf(sc[i] - m) * inv;
}

// ---------------------------------------------------------------------------
// K4: node aggregation + 3-layer MLP. One block per (b,i) node.
// ---------------------------------------------------------------------------
__global__ void __launch_bounds__(128) k_node(
    const float* __restrict__ Wg1, const float* __restrict__ bg1,
    const float* __restrict__ Wg2, const float* __restrict__ bg2,
    const float* __restrict__ Wout, const float* __restrict__ bout,
    float* __restrict__ out)
{
    __shared__ float nsm[128], g1s[64], g2s[64];
    const int bi = blockIdx.x;
    const int tid = threadIdx.x;
    const int h = tid & 63, half = tid >> 6;

    const float* efa = g_efa + (size_t)bi * NN * HH;
    const float* aw  = g_attw + bi * NN;
    float a = 0.f;
    for (int j = half * 50; j < half * 50 + 50; ++j)
        a += efa[j * 64 + h] * aw[j];
    nsm[tid] = a;
    __syncthreads();
    if (tid < 64) nsm[tid] = nsm[tid] + nsm[tid + 64];
    __syncthreads();
    if (tid < 64) {
        float acc = bg1[tid];
        for (int i = 0; i < 64; ++i) acc += nsm[i] * Wg1[i * 64 + tid];
        g1s[tid] = fmaxf(acc, 0.f);
    }
    __syncthreads();
    if (tid < 64) {
        float acc = bg2[tid];
        for (int i = 0; i < 64; ++i) acc += g1s[i] * Wg2[i * 64 + tid];
        g2s[tid] = fmaxf(acc, 0.f);
    }
    __syncthreads();
    {
        float acc = bout[tid];
        for (int i = 0; i < 64; ++i) acc += g2s[i] * Wout[i * OO + tid];
        out[bi * OO + tid] = fmaxf(acc, 0.f);
    }
}

// ---------------------------------------------------------------------------
extern "C" void kernel_launch(void* const* d_in, const int* in_sizes, int n_in,
                              void* d_out, int out_size) {
    const float* ew   = (const float*)d_in[0];
    const float* We   = (const float*)d_in[1];
    const float* be   = (const float*)d_in[2];
    const float* w1   = (const float*)d_in[3];
    const float* b1   = (const float*)d_in[4];
    const float* w2   = (const float*)d_in[5];
    const float* b2   = (const float*)d_in[6];
    const float* Wt1  = (const float*)d_in[7];
    const float* bt1  = (const float*)d_in[8];
    const float* Wt2  = (const float*)d_in[9];
    const float* bt2  = (const float*)d_in[10];
    const float* Ws1  = (const float*)d_in[11];
    const float* bs1  = (const float*)d_in[12];
    const float* Ws2  = (const float*)d_in[13];
    const float* bs2  = (const float*)d_in[14];
    const float* Wg1  = (const float*)d_in[15];
    const float* bg1  = (const float*)d_in[16];
    const float* Wg2  = (const float*)d_in[17];
    const float* bg2  = (const float*)d_in[18];
    const float* Wout = (const float*)d_in[19];
    const float* bout = (const float*)d_in[20];
    float* out = (float*)d_out;

    const int smem_bytes = S_TOTAL * 4;  // 184192 B
    cudaFuncSetAttribute(k_edge, cudaFuncAttributeMaxDynamicSharedMemorySize,
                         smem_bytes);

    k_prep<<<1, 256>>>(w1, We, be);
    k_edge<<<148, NTHREADS, smem_bytes>>>(ew, b1, w2, b2, Wt1, bt1, Wt2, bt2,
                                          Ws1, bs1, Ws2, bs2);
    k_spatial<<<BB, 1024>>>();
    k_node<<<BB * NN, 128>>>(Wg1, bg1, Wg2, bg2, Wout, bout, out);
}

// round 6
// speedup vs baseline: 3.4366x; 1.2887x over previous
#include <cuda_runtime.h>
#include <cuda_bf16.h>
#include <math.h>
#include <stdint.h>

// Problem constants
#define BB 4
#define NN 100
#define TT 20
#define HH 64
#define OO 128
#define MM 40000            // B*N*N edges
#define NE 16               // edges per group
#define NGROUPS (MM/NE)     // 2500
#define ESLOT 22            // [0]=left pad, [1..20]=t, [21]=right pad
#define XROW2 (NE*ESLOT+1)  // 353 words/row, odd for bank spread
#define NTHREADS 512

// Scratch
__device__ float g_efa[MM * HH];   // 10.24 MB
__device__ float g_score[MM];
__device__ float g_attw[MM];
__device__ float g_A1[HH * 3];
__device__ float g_Bb[HH * 3];

// ---- helpers ---------------------------------------------------------------
__device__ __forceinline__ float tanha(float x) {
    float y;
    asm("tanh.approx.f32 %0, %1;" : "=f"(y) : "f"(x));
    return y;
}
__device__ __forceinline__ uint32_t f2tf32(float x) {
    uint32_t r;
    asm("cvt.rna.tf32.f32 %0, %1;" : "=r"(r) : "f"(x));
    return r;
}
// pack two f32 -> bf16x2 word; 'lo' lands in low 16 bits (first element)
__device__ __forceinline__ uint32_t pkbf2(float lo, float hi) {
    uint32_t r;
    asm("cvt.rn.bf16x2.f32 %0, %1, %2;" : "=r"(r) : "f"(hi), "f"(lo));
    return r;
}
__device__ __forceinline__ float bfu_lo(uint32_t w) {
    return __uint_as_float(w << 16);
}
__device__ __forceinline__ float bfu_hi(uint32_t w) {
    return __uint_as_float(w & 0xffff0000u);
}
// m16n8k16 bf16 MMA (A row-major frags, B col-major packed pairs along k)
__device__ __forceinline__ void mma_bf16(float d[4], uint4 a,
                                         uint32_t b0, uint32_t b1) {
    asm volatile(
        "mma.sync.aligned.m16n8k16.row.col.f32.bf16.bf16.f32 "
        "{%0,%1,%2,%3},{%4,%5,%6,%7},{%8,%9},{%0,%1,%2,%3};"
        : "+f"(d[0]), "+f"(d[1]), "+f"(d[2]), "+f"(d[3])
        : "r"(a.x), "r"(a.y), "r"(a.z), "r"(a.w), "r"(b0), "r"(b1));
}
// m16n8k8 tf32 MMA (spatial-score path)
__device__ __forceinline__ void mma_tf32(float d[4], uint4 a,
                                         uint32_t b0, uint32_t b1) {
    asm volatile(
        "mma.sync.aligned.m16n8k8.row.col.f32.tf32.tf32.f32 "
        "{%0,%1,%2,%3},{%4,%5,%6,%7},{%8,%9},{%0,%1,%2,%3};"
        : "+f"(d[0]), "+f"(d[1]), "+f"(d[2]), "+f"(d[3])
        : "r"(a.x), "r"(a.y), "r"(a.z), "r"(a.w), "r"(b0), "r"(b1));
}

// ---------------------------------------------------------------------------
// K0: fold conv1 weights against the rank-1 edge embedding
// ---------------------------------------------------------------------------
__global__ void k_prep(const float* __restrict__ w1,
                       const float* __restrict__ We,
                       const float* __restrict__ be) {
    int idx = threadIdx.x;
    if (idx < HH * 3) {
        int h = idx / 3, k = idx % 3;
        float a = 0.f, c = 0.f;
        for (int i = 0; i < HH; ++i) {
            float w = w1[(h * HH + i) * 3 + k];
            a += w * We[i];
            c += w * be[i];
        }
        g_A1[idx] = a;
        g_Bb[idx] = c;
    }
}

// ---------------------------------------------------------------------------
// K2: fused per-edge temporal pipeline.
// conv2 bf16 MMA; Wt1 bf16 MMA on packed x2 (pairs (h,h+8), perm in A-frags);
// spatial score via tf32 MMA over efa.
// SMEM word offsets:
#define S_W2F  0            // 6144 : conv2 A-frags (bf16x2) [ht][kb12][lane][4]
#define S_WT1F 6144         // 2048 : Wt1 A-frags (bf16x2, sigma-perm) [ht][kb4][lane][4]
#define S_WS1F 8192         // 4096 : Ws1 A-frags (tf32) [ht][kb8][lane][4]
#define S_XS   12288        // 11296: packed bf16x2 tile, 32 pair-rows x XROW2
#define S_ES   23584        // 320
#define S_ATT  23904        // 320
#define S_SPART 24224       // 1280 : 4 htiles x 320
#define S_EFA  25504        // 1024
#define S_SS2  26528        // 64   : 4 htiles x 16 edges
#define S_TOTAL 26592       // words -> 106368 B
// ---------------------------------------------------------------------------
extern __shared__ float smem[];

__global__ void __launch_bounds__(NTHREADS, 1) k_edge(
    const float* __restrict__ ew,   const float* __restrict__ b1,
    const float* __restrict__ w2,   const float* __restrict__ b2,
    const float* __restrict__ Wt1,  const float* __restrict__ bt1,
    const float* __restrict__ Wt2,  const float* __restrict__ bt2,
    const float* __restrict__ Ws1,  const float* __restrict__ bs1,
    const float* __restrict__ Ws2,  const float* __restrict__ bs2)
{
    uint32_t* w2f  = (uint32_t*)(smem + S_W2F);
    uint32_t* wt1f = (uint32_t*)(smem + S_WT1F);
    float* ws1f  = smem + S_WS1F;
    uint32_t* xsu = (uint32_t*)(smem + S_XS);
    float* e_s   = smem + S_ES;
    float* att_s = smem + S_ATT;
    float* spart = smem + S_SPART;
    float* efa_s = smem + S_EFA;
    float* ss2   = smem + S_SS2;

    const int tid  = threadIdx.x;
    const int w    = tid >> 5;
    const int lane = tid & 31;
    const int htile = w & 3;       // 16 h-rows each
    const int nhalf = w >> 2;      // 0..3, 80 n-cols each
    const int gid  = lane >> 2;    // 0..7
    const int tig  = lane & 3;     // 0..3

    // ---- one-time init: conv2 bf16 A-frags (single, no split) ---------------
    for (int f = tid; f < 4 * 12 * 32; f += NTHREADS) {
        int ht = f / 384, rem = f % 384, kb = rem / 32, ln = rem % 32;
        int r = ht * 16 + (ln >> 2);
        int k0 = (ln & 3) * 2;
        int kk = kb >> 2, ibase = (kb & 3) * 16;
        #pragma unroll
        for (int j = 0; j < 4; ++j) {
            int h  = r + (j & 1) * 8;
            int kl = k0 + (j >> 1) * 8;
            float v0 = w2[(h * 64 + ibase + kl) * 3 + kk];
            float v1 = w2[(h * 64 + ibase + kl + 1) * 3 + kk];
            w2f[f * 4 + j] = pkbf2(v0, v1);
        }
    }
    // Wt1 bf16 A-frags with sigma k-permutation: pair P holds h_in
    // sigma(2P) = (P>>3)*16 + (P&7), sigma(2P+1) = sigma(2P) + 8
    for (int f = tid; f < 4 * 4 * 32; f += NTHREADS) {
        int ht = f / 128, rem = f % 128, kb = rem / 32, ln = rem % 32;
        int r = ht * 16 + (ln >> 2);
        int tg = ln & 3;
        #pragma unroll
        for (int j = 0; j < 4; ++j) {
            int P = kb * 8 + tg + (j >> 1) * 4;
            int hh = r + (j & 1) * 8;
            int s = (P >> 3) * 16 + (P & 7);
            wt1f[f * 4 + j] = pkbf2(Wt1[s * 64 + hh], Wt1[(s + 8) * 64 + hh]);
        }
    }
    // Ws1 tf32 A-frags (natural k order): A[hout][hin] = Ws1[hin*64+hout]
    for (int f = tid; f < 4 * 8 * 32; f += NTHREADS) {
        int ht = f / 256, rem = f % 256, kb = rem / 32, ln = rem % 32;
        int base_r = ht * 16 + (ln >> 2);
        int base_c = kb * 8 + (ln & 3);
        #pragma unroll
        for (int j = 0; j < 4; ++j) {
            int h = base_r + (j & 1) * 8;
            int i = base_c + (j >> 1) * 4;
            ws1f[f * 4 + j] = __uint_as_float(f2tf32(Ws1[i * 64 + h]));
        }
    }
    // zero pad words of the packed tile (32 pair-rows), never overwritten
    for (int f = tid; f < 32 * 2 * NE; f += NTHREADS) {
        int pr = f / (2 * NE), p = f % (2 * NE);
        int e = p >> 1, side = p & 1;
        xsu[pr * XROW2 + e * ESLOT + side * 21] = 0u;
    }

    // ---- per-thread constant maps -------------------------------------------
    int cq[10];
    #pragma unroll
    for (int q = 0; q < 10; ++q) {
        int n = nhalf * 80 + q * 8 + gid;
        cq[q] = (n / 20) * ESLOT + 1 + (n % 20);
    }
    const int r0 = htile * 16 + gid;   // D rows r0, r0+8
    const float b2_0 = b2[r0],  b2_1 = b2[r0 + 8];
    const float bt1_0 = bt1[r0], bt1_1 = bt1[r0 + 8];
    const float wt2_0 = Wt2[r0], wt2_1 = Wt2[r0 + 8];
    const float bs1_0 = bs1[r0], bs1_1 = bs1[r0 + 8];
    const float ws2_0 = Ws2[r0], ws2_1 = Ws2[r0 + 8];
    const float bt2v = bt2[0];
    const float bs2v = bs2[0];

    // x1-stage mapping: thread -> channel pair (2pr, 2pr+1), one edge
    const int pr = tid >> 4;           // 0..31
    const int xe = tid & 15;           // edge 0..15
    const int c0 = pr * 2, c1 = c0 + 1;
    float a1k0[3], a1k1[3];
    float s0c = 0.f, s1c = 0.f;
    #pragma unroll
    for (int k = 0; k < 3; ++k) {
        a1k0[k] = g_A1[c0 * 3 + k];  a1k1[k] = g_A1[c1 * 3 + k];
        s0c += g_Bb[c0 * 3 + k];     s1c += g_Bb[c1 * 3 + k];
    }
    const float c3_0 = b1[c0] + s0c;
    const float c3_1 = b1[c1] + s1c;
    const float ca_0 = c3_0 - g_Bb[c0 * 3 + 0];   // t = 0
    const float ca_1 = c3_1 - g_Bb[c1 * 3 + 0];
    const float cb_0 = c3_0 - g_Bb[c0 * 3 + 2];   // t = 19
    const float cb_1 = c3_1 - g_Bb[c1 * 3 + 2];

    // efa-stage mapping: one (edge, pair-row) per thread
    const int fe = tid >> 5;           // edge 0..15 (warp == edge)
    const int fp = lane;               // pair-row 0..31
    const int fh0 = (fp >> 3) * 16 + (fp & 7);
    const int fh1 = fh0 + 8;

    // prefetch first group's edge scalars
    float epref = 0.f;
    if (blockIdx.x < NGROUPS && tid < NE * TT)
        epref = ew[blockIdx.x * (NE * TT) + tid];

    for (int g = blockIdx.x; g < NGROUPS; g += gridDim.x) {
        const int m0 = g * NE;

        if (tid < NE * TT) e_s[tid] = epref;
        const int gn = g + gridDim.x;
        if (gn < NGROUPS && tid < NE * TT)
            epref = ew[gn * (NE * TT) + tid];
        __syncthreads();

        // ---- x1 = relu(folded conv1), packed bf16x2 by channel pair ----------
        {
            const float* ep = e_s + xe * TT;
            uint32_t* oa = xsu + pr * XROW2 + xe * ESLOT + 1;
            #pragma unroll
            for (int t = 0; t < TT; ++t) {
                float x0, x1v;
                if (t == 0) {
                    x0 = ca_0 + a1k0[1] * ep[0] + a1k0[2] * ep[1];
                    x1v = ca_1 + a1k1[1] * ep[0] + a1k1[2] * ep[1];
                } else if (t == 19) {
                    x0 = cb_0 + a1k0[0] * ep[18] + a1k0[1] * ep[19];
                    x1v = cb_1 + a1k1[0] * ep[18] + a1k1[1] * ep[19];
                } else {
                    x0 = c3_0 + a1k0[0]*ep[t-1] + a1k0[1]*ep[t] + a1k0[2]*ep[t+1];
                    x1v = c3_1 + a1k1[0]*ep[t-1] + a1k1[1]*ep[t] + a1k1[2]*ep[t+1];
                }
                oa[t] = pkbf2(fmaxf(x0, 0.f), fmaxf(x1v, 0.f));
            }
        }
        __syncthreads();

        // ---- conv2 via single bf16 MMA: D[64 x 320], K = 192 ------------------
        float d[10][4];
        #pragma unroll
        for (int q = 0; q < 10; ++q)
            #pragma unroll
            for (int j = 0; j < 4; ++j) d[q][j] = 0.f;

        #pragma unroll 1
        for (int kb = 0; kb < 12; ++kb) {
            const int fo = ((htile * 12 + kb) * 32 + lane) * 4;
            const uint4 A = *(const uint4*)(w2f + fo);
            const int prow = (kb & 3) * 8 + tig;
            const int koff = (kb >> 2) - 1;
            const uint32_t* bp = xsu + prow * XROW2 + koff;
            #pragma unroll
            for (int q = 0; q < 10; ++q) {
                uint32_t b0 = bp[cq[q]];
                uint32_t b1 = bp[cq[q] + 4 * XROW2];
                mma_bf16(d[q], A, b0, b1);
            }
        }
        __syncthreads();  // all B reads done before overwriting the tile

        // ---- epilogue: x2 = relu(d+b2) packed (r0, r0+8) -> pair-row ----------
        {
            uint32_t* op = xsu + (htile * 8 + gid) * XROW2;
            #pragma unroll
            for (int q = 0; q < 10; ++q) {
                int n0 = nhalf * 80 + q * 8 + tig * 2;
                int col0 = (n0 / 20) * ESLOT + 1 + (n0 % 20);
                int n1 = n0 + 1;
                int col1 = (n1 / 20) * ESLOT + 1 + (n1 % 20);
                op[col0] = pkbf2(fmaxf(d[q][0] + b2_0, 0.f),
                                 fmaxf(d[q][2] + b2_1, 0.f));
                op[col1] = pkbf2(fmaxf(d[q][1] + b2_0, 0.f),
                                 fmaxf(d[q][3] + b2_1, 0.f));
            }
        }
        __syncthreads();

        // ---- u_pre = Wt1^T @ x2 via bf16 MMA on packed tile -------------------
        float d2[10][4];
        #pragma unroll
        for (int q = 0; q < 10; ++q)
            #pragma unroll
            for (int j = 0; j < 4; ++j) d2[q][j] = 0.f;

        #pragma unroll 1
        for (int kb = 0; kb < 4; ++kb) {
            const int fo = ((htile * 4 + kb) * 32 + lane) * 4;
            const uint4 A = *(const uint4*)(wt1f + fo);
            const uint32_t* bp = xsu + (kb * 8 + tig) * XROW2;
            #pragma unroll
            for (int q = 0; q < 10; ++q) {
                uint32_t b0 = bp[cq[q]];
                uint32_t b1 = bp[cq[q] + 4 * XROW2];
                mma_bf16(d2[q], A, b0, b1);
            }
        }

        // ---- score partials: p[n] = sum_h tanh(u+bt1)*Wt2 ---------------------
        #pragma unroll
        for (int q = 0; q < 10; ++q) {
            float s0 = tanha(d2[q][0] + bt1_0) * wt2_0
                     + tanha(d2[q][2] + bt1_1) * wt2_1;
            float s1 = tanha(d2[q][1] + bt1_0) * wt2_0
                     + tanha(d2[q][3] + bt1_1) * wt2_1;
            #pragma unroll
            for (int off = 4; off < 32; off <<= 1) {
                s0 += __shfl_xor_sync(0xffffffffu, s0, off);
                s1 += __shfl_xor_sync(0xffffffffu, s1, off);
            }
            if (lane < 4) {
                int n0 = nhalf * 80 + q * 8 + lane * 2;
                spart[htile * 320 + n0]     = s0;
                spart[htile * 320 + n0 + 1] = s1;
            }
        }
        __syncthreads();

        // ---- temporal softmax: warp w handles edge w --------------------------
        {
            float v = -1e30f;
            if (lane < TT) {
                int n = w * TT + lane;
                v = spart[n] + spart[320 + n] + spart[640 + n] + spart[960 + n]
                  + bt2v;
            }
            float mx = v;
            #pragma unroll
            for (int off = 16; off; off >>= 1)
                mx = fmaxf(mx, __shfl_xor_sync(0xffffffffu, mx, off));
            float ev = (lane < TT) ? expf(v - mx) : 0.f;
            float sum = ev;
            #pragma unroll
            for (int off = 16; off; off >>= 1)
                sum += __shfl_xor_sync(0xffffffffu, sum, off);
            if (lane < TT) att_s[w * TT + lane] = ev / sum;
        }
        __syncthreads();

        // ---- efa: one (edge, pair) per thread; unpack bf16x2 ------------------
        {
            const uint32_t* xr = xsu + fp * XROW2 + fe * ESLOT + 1;
            const float* at = att_s + fe * TT;
            float a0 = 0.f, a1 = 0.f;
            #pragma unroll
            for (int t = 0; t < TT; ++t) {
                uint32_t wd = xr[t];
                float av = at[t];
                a0 += bfu_lo(wd) * av;
                a1 += bfu_hi(wd) * av;
            }
            efa_s[fe * 64 + fh0] = a0;
            efa_s[fe * 64 + fh1] = a1;
            g_efa[(m0 + fe) * 64 + fh0] = a0;
            g_efa[(m0 + fe) * 64 + fh1] = a1;
        }
        __syncthreads();

        // ---- spatial score via tf32 MMA: D[64h x 16e], K = 64 -----------------
        if (w < 8) {
            const int nt = w >> 2;     // 0..1 (8 edges each)
            const int ht2 = w & 3;
            float d3[4] = {0.f, 0.f, 0.f, 0.f};
            #pragma unroll
            for (int kb = 0; kb < 8; ++kb) {
                const int fo = ((ht2 * 8 + kb) * 32 + lane) * 4;
                const uint4 A = *(const uint4*)(ws1f + fo);
                const float* bp = efa_s + (nt * 8 + gid) * 64 + kb * 8 + tig;
                uint32_t b0 = __float_as_uint(bp[0]);
                uint32_t b1 = __float_as_uint(bp[4]);
                mma_tf32(d3, A, b0, b1);
            }
            const int rr0 = ht2 * 16 + gid;
            float v0 = tanha(d3[0] + bs1[rr0]) * Ws2[rr0]
                     + tanha(d3[2] + bs1[rr0 + 8]) * Ws2[rr0 + 8];
            float v1 = tanha(d3[1] + bs1[rr0]) * Ws2[rr0]
                     + tanha(d3[3] + bs1[rr0 + 8]) * Ws2[rr0 + 8];
            #pragma unroll
            for (int off = 4; off < 32; off <<= 1) {
                v0 += __shfl_xor_sync(0xffffffffu, v0, off);
                v1 += __shfl_xor_sync(0xffffffffu, v1, off);
            }
            if (lane < 4) {
                int e0 = nt * 8 + lane * 2;
                ss2[ht2 * 16 + e0]     = v0;
                ss2[ht2 * 16 + e0 + 1] = v1;
            }
        }
        __syncthreads();
        if (tid < NE)
            g_score[m0 + tid] = ss2[tid] + ss2[16 + tid] + ss2[32 + tid]
                              + ss2[48 + tid] + bs2v;
    }
}

// ---------------------------------------------------------------------------
// K3: per-batch spatial softmax over N*N = 10000 scores
// ---------------------------------------------------------------------------
__global__ void __launch_bounds__(1024) k_spatial() {
    __shared__ float red[1024];
    __shared__ float mx_s, z_s;
    int b = blockIdx.x, tid = threadIdx.x;
    const float* sc = g_score + b * (NN * NN);

    float mx = -1e30f;
    for (int i = tid; i < NN * NN; i += 1024) mx = fmaxf(mx, sc[i]);
    red[tid] = mx;
    __syncthreads();
    for (int s = 512; s; s >>= 1) {
        if (tid < s) red[tid] = fmaxf(red[tid], red[tid + s]);
        __syncthreads();
    }
    if (tid == 0) mx_s = red[0];
    __syncthreads();
    float m = mx_s, z = 0.f;
    for (int i = tid; i < NN * NN; i += 1024) z += expf(sc[i] - m);
    red[tid] = z;
    __syncthreads();
    for (int s = 512; s; s >>= 1) {
        if (tid < s) red[tid] += red[tid + s];
        __syncthreads();
    }
    if (tid == 0) z_s = red[0];
    __syncthreads();
    float inv = 1.f / z_s;
    for (int i = tid; i < NN * NN; i += 1024)
        g_attw[b * (NN * NN) + i] = expf(sc[i] - m) * inv;
}

// ---------------------------------------------------------------------------
// K4: node aggregation + 3-layer MLP. One block per (b,i) node.
// ---------------------------------------------------------------------------
__global__ void __launch_bounds__(128) k_node(
    const float* __restrict__ Wg1, const float* __restrict__ bg1,
    const float* __restrict__ Wg2, const float* __restrict__ bg2,
    const float* __restrict__ Wout, const float* __restrict__ bout,
    float* __restrict__ out)
{
    __shared__ float nsm[128], g1s[64], g2s[64];
    const int bi = blockIdx.x;
    const int tid = threadIdx.x;
    const int h = tid & 63, half = tid >> 6;

    const float* efa = g_efa + (size_t)bi * NN * HH;
    const float* aw  = g_attw + bi * NN;
    float a = 0.f;
    for (int j = half * 50; j < half * 50 + 50; ++j)
        a += efa[j * 64 + h] * aw[j];
    nsm[tid] = a;
    __syncthreads();
    if (tid < 64) nsm[tid] = nsm[tid] + nsm[tid + 64];
    __syncthreads();
    if (tid < 64) {
        float acc = bg1[tid];
        for (int i = 0; i < 64; ++i) acc += nsm[i] * Wg1[i * 64 + tid];
        g1s[tid] = fmaxf(acc, 0.f);
    }
    __syncthreads();
    if (tid < 64) {
        float acc = bg2[tid];
        for (int i = 0; i < 64; ++i) acc += g1s[i] * Wg2[i * 64 + tid];
        g2s[tid] = fmaxf(acc, 0.f);
    }
    __syncthreads();
    {
        float acc = bout[tid];
        for (int i = 0; i < 64; ++i) acc += g2s[i] * Wout[i * OO + tid];
        out[bi * OO + tid] = fmaxf(acc, 0.f);
    }
}

// ---------------------------------------------------------------------------
extern "C" void kernel_launch(void* const* d_in, const int* in_sizes, int n_in,
                              void* d_out, int out_size) {
    const float* ew   = (const float*)d_in[0];
    const float* We   = (const float*)d_in[1];
    const float* be   = (const float*)d_in[2];
    const float* w1   = (const float*)d_in[3];
    const float* b1   = (const float*)d_in[4];
    const float* w2   = (const float*)d_in[5];
    const float* b2   = (const float*)d_in[6];
    const float* Wt1  = (const float*)d_in[7];
    const float* bt1  = (const float*)d_in[8];
    const float* Wt2  = (const float*)d_in[9];
    const float* bt2  = (const float*)d_in[10];
    const float* Ws1  = (const float*)d_in[11];
    const float* bs1  = (const float*)d_in[12];
    const float* Ws2  = (const float*)d_in[13];
    const float* bs2  = (const float*)d_in[14];
    const float* Wg1  = (const float*)d_in[15];
    const float* bg1  = (const float*)d_in[16];
    const float* Wg2  = (const float*)d_in[17];
    const float* bg2  = (const float*)d_in[18];
    const float* Wout = (const float*)d_in[19];
    const float* bout = (const float*)d_in[20];
    float* out = (float*)d_out;

    const int smem_bytes = S_TOTAL * 4;  // 106368 B
    cudaFuncSetAttribute(k_edge, cudaFuncAttributeMaxDynamicSharedMemorySize,
                         smem_bytes);

    k_prep<<<1, 256>>>(w1, We, be);
    k_edge<<<148, NTHREADS, smem_bytes>>>(ew, b1, w2, b2, Wt1, bt1, Wt2, bt2,
                                          Ws1, bs1, Ws2, bs2);
    k_spatial<<<BB, 1024>>>();
    k_node<<<BB * NN, 128>>>(Wg1, bg1, Wg2, bg2, Wout, bout, out);
}

// round 7
// speedup vs baseline: 6.0079x; 1.7482x over previous
#include <cuda_runtime.h>
#include <cuda_bf16.h>
#include <math.h>
#include <stdint.h>

// Problem constants
#define BB 4
#define NN 100
#define TT 20
#define HH 64
#define OO 128
#define MM 40000            // B*N*N edges
#define NE 16               // edges per group
#define NGROUPS (MM/NE)     // 2500
#define ESLOT 22            // [0]=left pad, [1..20]=t, [21]=right pad
#define XR 360              // row stride (=8 mod 32 for conflict-free MMA gathers)
#define NTHREADS 512

// Scratch
__device__ float g_efa[MM * HH];   // 10.24 MB
__device__ float g_score[MM];
__device__ float g_attw[MM];
__device__ float g_A1[HH * 3];
__device__ float g_Bb[HH * 3];

// ---- helpers ---------------------------------------------------------------
__device__ __forceinline__ float tanha(float x) {
    float y;
    asm("tanh.approx.f32 %0, %1;" : "=f"(y) : "f"(x));
    return y;
}
__device__ __forceinline__ uint32_t f2tf32(float x) {
    uint32_t r;
    asm("cvt.rna.tf32.f32 %0, %1;" : "=r"(r) : "f"(x));
    return r;
}
// pack two f32 -> bf16x2 word; 'lo' lands in low 16 bits (first element)
__device__ __forceinline__ uint32_t pkbf2(float lo, float hi) {
    uint32_t r;
    asm("cvt.rn.bf16x2.f32 %0, %1, %2;" : "=r"(r) : "f"(hi), "f"(lo));
    return r;
}
__device__ __forceinline__ float bfu_lo(uint32_t w) {
    return __uint_as_float(w << 16);
}
__device__ __forceinline__ float bfu_hi(uint32_t w) {
    return __uint_as_float(w & 0xffff0000u);
}
__device__ __forceinline__ void mma_bf16(float d[4], uint4 a,
                                         uint32_t b0, uint32_t b1) {
    asm volatile(
        "mma.sync.aligned.m16n8k16.row.col.f32.bf16.bf16.f32 "
        "{%0,%1,%2,%3},{%4,%5,%6,%7},{%8,%9},{%0,%1,%2,%3};"
        : "+f"(d[0]), "+f"(d[1]), "+f"(d[2]), "+f"(d[3])
        : "r"(a.x), "r"(a.y), "r"(a.z), "r"(a.w), "r"(b0), "r"(b1));
}
__device__ __forceinline__ void mma_tf32(float d[4], uint4 a,
                                         uint32_t b0, uint32_t b1) {
    asm volatile(
        "mma.sync.aligned.m16n8k8.row.col.f32.tf32.tf32.f32 "
        "{%0,%1,%2,%3},{%4,%5,%6,%7},{%8,%9},{%0,%1,%2,%3};"
        : "+f"(d[0]), "+f"(d[1]), "+f"(d[2]), "+f"(d[3])
        : "r"(a.x), "r"(a.y), "r"(a.z), "r"(a.w), "r"(b0), "r"(b1));
}

// ---------------------------------------------------------------------------
// K0: fold conv1 weights against the rank-1 edge embedding
// ---------------------------------------------------------------------------
__global__ void k_prep(const float* __restrict__ w1,
                       const float* __restrict__ We,
                       const float* __restrict__ be) {
    int idx = threadIdx.x;
    if (idx < HH * 3) {
        int h = idx / 3, k = idx % 3;
        float a = 0.f, c = 0.f;
        for (int i = 0; i < HH; ++i) {
            float w = w1[(h * HH + i) * 3 + k];
            a += w * We[i];
            c += w * be[i];
        }
        g_A1[idx] = a;
        g_Bb[idx] = c;
    }
}

// ---------------------------------------------------------------------------
// K2: fused per-edge pipeline; conflict-free MMA gathers via residue-perm.
// SMEM word offsets:
#define S_W2F  0            // 6144 : conv2 A-frags (bf16x2) [ht][kb12][lane][4]
#define S_WT1F 6144         // 2048 : Wt1 A-frags (bf16x2, sigma-perm)
#define S_WS1F 8192         // 4096 : Ws1 A-frags (tf32)
#define S_XS   12288        // 11520: packed bf16x2 tile, 32 pair-rows x XR
#define S_ES   23808        // 320
#define S_ATT  24128        // 320
#define S_SPART 24448       // 1408 : 4 htiles x 352 (indexed by column)
#define S_EFA  25856        // 1088 : 16 edges x 68 (padded stride)
#define S_SS2  26944        // 64
#define S_TOTAL 27008       // words -> 108032 B
// ---------------------------------------------------------------------------
extern __shared__ float smem[];

__global__ void __launch_bounds__(NTHREADS, 1) k_edge(
    const float* __restrict__ ew,   const float* __restrict__ b1,
    const float* __restrict__ w2,   const float* __restrict__ b2,
    const float* __restrict__ Wt1,  const float* __restrict__ bt1,
    const float* __restrict__ Wt2,  const float* __restrict__ bt2,
    const float* __restrict__ Ws1,  const float* __restrict__ bs1,
    const float* __restrict__ Ws2,  const float* __restrict__ bs2)
{
    uint32_t* w2f  = (uint32_t*)(smem + S_W2F);
    uint32_t* wt1f = (uint32_t*)(smem + S_WT1F);
    float* ws1f  = smem + S_WS1F;
    uint32_t* xsu = (uint32_t*)(smem + S_XS);
    float* e_s   = smem + S_ES;
    float* att_s = smem + S_ATT;
    float* spart = smem + S_SPART;
    float* efa_s = smem + S_EFA;
    float* ss2   = smem + S_SS2;

    const int tid  = threadIdx.x;
    const int w    = tid >> 5;
    const int lane = tid & 31;
    const int htile = w & 3;       // 16 h-rows each
    const int nhalf = w >> 2;      // 0..3, one 4-edge window (80 cols)
    const int gid  = lane >> 2;    // 0..7
    const int tig  = lane & 3;     // 0..3

    // ---- one-time init: conv2 bf16 A-frags ----------------------------------
    for (int f = tid; f < 4 * 12 * 32; f += NTHREADS) {
        int ht = f / 384, rem = f % 384, kb = rem / 32, ln = rem % 32;
        int r = ht * 16 + (ln >> 2);
        int k0 = (ln & 3) * 2;
        int kk = kb >> 2, ibase = (kb & 3) * 16;
        #pragma unroll
        for (int j = 0; j < 4; ++j) {
            int h  = r + (j & 1) * 8;
            int kl = k0 + (j >> 1) * 8;
            float v0 = w2[(h * 64 + ibase + kl) * 3 + kk];
            float v1 = w2[(h * 64 + ibase + kl + 1) * 3 + kk];
            w2f[f * 4 + j] = pkbf2(v0, v1);
        }
    }
    // Wt1 bf16 A-frags with sigma k-permutation (pair P -> h_in pair)
    for (int f = tid; f < 4 * 4 * 32; f += NTHREADS) {
        int ht = f / 128, rem = f % 128, kb = rem / 32, ln = rem % 32;
        int r = ht * 16 + (ln >> 2);
        int tg = ln & 3;
        #pragma unroll
        for (int j = 0; j < 4; ++j) {
            int P = kb * 8 + tg + (j >> 1) * 4;
            int hh = r + (j & 1) * 8;
            int s = (P >> 3) * 16 + (P & 7);
            wt1f[f * 4 + j] = pkbf2(Wt1[s * 64 + hh], Wt1[(s + 8) * 64 + hh]);
        }
    }
    // Ws1 tf32 A-frags
    for (int f = tid; f < 4 * 8 * 32; f += NTHREADS) {
        int ht = f / 256, rem = f % 256, kb = rem / 32, ln = rem % 32;
        int base_r = ht * 16 + (ln >> 2);
        int base_c = kb * 8 + (ln & 3);
        #pragma unroll
        for (int j = 0; j < 4; ++j) {
            int h = base_r + (j & 1) * 8;
            int i = base_c + (j >> 1) * 4;
            ws1f[f * 4 + j] = __uint_as_float(f2tf32(Ws1[i * 64 + h]));
        }
    }
    // zero pad words of the packed tile (32 pair-rows)
    for (int f = tid; f < 32 * 2 * NE; f += NTHREADS) {
        int pr = f / (2 * NE), p = f % (2 * NE);
        int e = p >> 1, side = p & 1;
        xsu[pr * XR + e * ESLOT + side * 21] = 0u;
    }

    // ---- residue-perm column LUTs (conflict-free MMA gathers) ---------------
    // Window = 4 edges (80 cols). MMA q, position p take the q-th column in the
    // window with col == p (mod 8). Gather lane needs p=gid; D lanes need
    // p=2*tig, 2*tig+1.
    int cq[10], dc0[10], dc1[10];
    {
        const int wb = nhalf * 4 * ESLOT;
        int n0 = 0, n1 = 0, n2 = 0;
        for (int e4 = 0; e4 < 4; ++e4)
            for (int t = 0; t < TT; ++t) {
                int col = wb + e4 * ESLOT + 1 + t;
                int r8 = col & 7;
                if (r8 == gid)            cq[n0++] = col;
                if (r8 == 2 * tig)        dc0[n1++] = col;
                if (r8 == 2 * tig + 1)    dc1[n2++] = col;
            }
    }
    const int r0 = htile * 16 + gid;   // D rows r0, r0+8
    const float b2_0 = b2[r0],  b2_1 = b2[r0 + 8];
    const float bt1_0 = bt1[r0], bt1_1 = bt1[r0 + 8];
    const float wt2_0 = Wt2[r0], wt2_1 = Wt2[r0 + 8];
    const float bt2v = bt2[0];
    const float bs2v = bs2[0];

    // x1-stage mapping: thread -> channel pair (2pr, 2pr+1), one edge
    const int pr = tid >> 4;           // 0..31
    const int xe = tid & 15;           // edge 0..15
    const int c0 = pr * 2, c1 = c0 + 1;
    float a1k0[3], a1k1[3];
    float s0c = 0.f, s1c = 0.f;
    #pragma unroll
    for (int k = 0; k < 3; ++k) {
        a1k0[k] = g_A1[c0 * 3 + k];  a1k1[k] = g_A1[c1 * 3 + k];
        s0c += g_Bb[c0 * 3 + k];     s1c += g_Bb[c1 * 3 + k];
    }
    const float c3_0 = b1[c0] + s0c;
    const float c3_1 = b1[c1] + s1c;
    const float ca_0 = c3_0 - g_Bb[c0 * 3 + 0];   // t = 0
    const float ca_1 = c3_1 - g_Bb[c1 * 3 + 0];
    const float cb_0 = c3_0 - g_Bb[c0 * 3 + 2];   // t = 19
    const float cb_1 = c3_1 - g_Bb[c1 * 3 + 2];

    // efa-stage mapping: warp covers 8 pair-rows x 4 edges (2-way conflicts max)
    const int fpr = (w & 3) * 8 + (lane & 7);     // pair-row 0..31
    const int fe  = (w >> 2) * 4 + (lane >> 3);   // edge 0..15
    const int fh0 = (fpr >> 3) * 16 + (fpr & 7);
    const int fh1 = fh0 + 8;

    // prefetch first group's edge scalars
    float epref = 0.f;
    if (blockIdx.x < NGROUPS && tid < NE * TT)
        epref = ew[blockIdx.x * (NE * TT) + tid];

    for (int g = blockIdx.x; g < NGROUPS; g += gridDim.x) {
        const int m0 = g * NE;

        if (tid < NE * TT) e_s[tid] = epref;
        const int gn = g + gridDim.x;
        if (gn < NGROUPS && tid < NE * TT)
            epref = ew[gn * (NE * TT) + tid];
        __syncthreads();

        // ---- x1 = relu(folded conv1), packed bf16x2 by channel pair ----------
        {
            const float* ep = e_s + xe * TT;
            uint32_t* oa = xsu + pr * XR + xe * ESLOT + 1;
            #pragma unroll
            for (int t = 0; t < TT; ++t) {
                float x0, x1v;
                if (t == 0) {
                    x0 = ca_0 + a1k0[1] * ep[0] + a1k0[2] * ep[1];
                    x1v = ca_1 + a1k1[1] * ep[0] + a1k1[2] * ep[1];
                } else if (t == 19) {
                    x0 = cb_0 + a1k0[0] * ep[18] + a1k0[1] * ep[19];
                    x1v = cb_1 + a1k1[0] * ep[18] + a1k1[1] * ep[19];
                } else {
                    x0 = c3_0 + a1k0[0]*ep[t-1] + a1k0[1]*ep[t] + a1k0[2]*ep[t+1];
                    x1v = c3_1 + a1k1[0]*ep[t-1] + a1k1[1]*ep[t] + a1k1[2]*ep[t+1];
                }
                oa[t] = pkbf2(fmaxf(x0, 0.f), fmaxf(x1v, 0.f));
            }
        }
        __syncthreads();

        // ---- conv2 via bf16 MMA: D[64 x 320], K = 192 (conflict-free B) ------
        float d[10][4];
        #pragma unroll
        for (int q = 0; q < 10; ++q)
            #pragma unroll
            for (int j = 0; j < 4; ++j) d[q][j] = 0.f;

        #pragma unroll 1
        for (int kb = 0; kb < 12; ++kb) {
            const int fo = ((htile * 12 + kb) * 32 + lane) * 4;
            const uint4 A = *(const uint4*)(w2f + fo);
            const int prow = (kb & 3) * 8 + tig;
            const int koff = (kb >> 2) - 1;
            const uint32_t* bp = xsu + prow * XR + koff;
            #pragma unroll
            for (int q = 0; q < 10; ++q) {
                uint32_t b0 = bp[cq[q]];
                uint32_t b1 = bp[cq[q] + 4 * XR];
                mma_bf16(d[q], A, b0, b1);
            }
        }
        __syncthreads();  // all B reads done before overwriting the tile

        // ---- epilogue: x2 = relu(d+b2) packed (r0, r0+8) -> pair-row ----------
        {
            uint32_t* op = xsu + (htile * 8 + gid) * XR;
            #pragma unroll
            for (int q = 0; q < 10; ++q) {
                op[dc0[q]] = pkbf2(fmaxf(d[q][0] + b2_0, 0.f),
                                   fmaxf(d[q][2] + b2_1, 0.f));
                op[dc1[q]] = pkbf2(fmaxf(d[q][1] + b2_0, 0.f),
                                   fmaxf(d[q][3] + b2_1, 0.f));
            }
        }
        __syncthreads();

        // ---- u_pre = Wt1^T @ x2 via bf16 MMA on packed tile -------------------
        float d2[10][4];
        #pragma unroll
        for (int q = 0; q < 10; ++q)
            #pragma unroll
            for (int j = 0; j < 4; ++j) d2[q][j] = 0.f;

        #pragma unroll 1
        for (int kb = 0; kb < 4; ++kb) {
            const int fo = ((htile * 4 + kb) * 32 + lane) * 4;
            const uint4 A = *(const uint4*)(wt1f + fo);
            const uint32_t* bp = xsu + (kb * 8 + tig) * XR;
            #pragma unroll
            for (int q = 0; q < 10; ++q) {
                uint32_t b0 = bp[cq[q]];
                uint32_t b1 = bp[cq[q] + 4 * XR];
                mma_bf16(d2[q], A, b0, b1);
            }
        }

        // ---- score partials (indexed by column) -------------------------------
        #pragma unroll
        for (int q = 0; q < 10; ++q) {
            float s0 = tanha(d2[q][0] + bt1_0) * wt2_0
                     + tanha(d2[q][2] + bt1_1) * wt2_1;
            float s1 = tanha(d2[q][1] + bt1_0) * wt2_0
                     + tanha(d2[q][3] + bt1_1) * wt2_1;
            #pragma unroll
            for (int off = 4; off < 32; off <<= 1) {
                s0 += __shfl_xor_sync(0xffffffffu, s0, off);
                s1 += __shfl_xor_sync(0xffffffffu, s1, off);
            }
            if (lane < 4) {
                spart[htile * 352 + dc0[q]] = s0;
                spart[htile * 352 + dc1[q]] = s1;
            }
        }
        __syncthreads();

        // ---- temporal softmax: warp w handles edge w --------------------------
        {
            float v = -1e30f;
            if (lane < TT) {
                int col = w * ESLOT + 1 + lane;
                v = spart[col] + spart[352 + col] + spart[704 + col]
                  + spart[1056 + col] + bt2v;
            }
            float mx = v;
            #pragma unroll
            for (int off = 16; off; off >>= 1)
                mx = fmaxf(mx, __shfl_xor_sync(0xffffffffu, mx, off));
            float ev = (lane < TT) ? expf(v - mx) : 0.f;
            float sum = ev;
            #pragma unroll
            for (int off = 16; off; off >>= 1)
                sum += __shfl_xor_sync(0xffffffffu, sum, off);
            if (lane < TT) att_s[w * TT + lane] = ev / sum;
        }
        __syncthreads();

        // ---- efa: (pair-row, edge) per thread; unpack bf16x2 ------------------
        {
            const uint32_t* xr = xsu + fpr * XR + fe * ESLOT + 1;
            const float* at = att_s + fe * TT;
            float a0 = 0.f, a1 = 0.f;
            #pragma unroll
            for (int t = 0; t < TT; ++t) {
                uint32_t wd = xr[t];
                float av = at[t];
                a0 += bfu_lo(wd) * av;
                a1 += bfu_hi(wd) * av;
            }
            efa_s[fe * 68 + fh0] = a0;
            efa_s[fe * 68 + fh1] = a1;
            g_efa[(m0 + fe) * 64 + fh0] = a0;
            g_efa[(m0 + fe) * 64 + fh1] = a1;
        }
        __syncthreads();

        // ---- spatial score via tf32 MMA: D[64h x 16e], K = 64 -----------------
        if (w < 8) {
            const int nt = w >> 2;     // 0..1 (8 edges each)
            const int ht2 = w & 3;
            float d3[4] = {0.f, 0.f, 0.f, 0.f};
            #pragma unroll
            for (int kb = 0; kb < 8; ++kb) {
                const int fo = ((ht2 * 8 + kb) * 32 + lane) * 4;
                const uint4 A = *(const uint4*)(ws1f + fo);
                const float* bp = efa_s + (nt * 8 + gid) * 68 + kb * 8 + tig;
                uint32_t b0 = __float_as_uint(bp[0]);
                uint32_t b1 = __float_as_uint(bp[4]);
                mma_tf32(d3, A, b0, b1);
            }
            const int rr0 = ht2 * 16 + gid;
            float v0 = tanha(d3[0] + bs1[rr0]) * Ws2[rr0]
                     + tanha(d3[2] + bs1[rr0 + 8]) * Ws2[rr0 + 8];
            float v1 = tanha(d3[1] + bs1[rr0]) * Ws2[rr0]
                     + tanha(d3[3] + bs1[rr0 + 8]) * Ws2[rr0 + 8];
            #pragma unroll
            for (int off = 4; off < 32; off <<= 1) {
                v0 += __shfl_xor_sync(0xffffffffu, v0, off);
                v1 += __shfl_xor_sync(0xffffffffu, v1, off);
            }
            if (lane < 4) {
                int e0 = nt * 8 + lane * 2;
                ss2[ht2 * 16 + e0]     = v0;
                ss2[ht2 * 16 + e0 + 1] = v1;
            }
        }
        __syncthreads();
        if (tid < NE)
            g_score[m0 + tid] = ss2[tid] + ss2[16 + tid] + ss2[32 + tid]
                              + ss2[48 + tid] + bs2v;
    }
}

// ---------------------------------------------------------------------------
// K3: per-batch spatial softmax over N*N = 10000 scores
// ---------------------------------------------------------------------------
__global__ void __launch_bounds__(1024) k_spatial() {
    __shared__ float red[1024];
    __shared__ float mx_s, z_s;
    int b = blockIdx.x, tid = threadIdx.x;
    const float* sc = g_score + b * (NN * NN);

    float mx = -1e30f;
    for (int i = tid; i < NN * NN; i += 1024) mx = fmaxf(mx, sc[i]);
    red[tid] = mx;
    __syncthreads();
    for (int s = 512; s; s >>= 1) {
        if (tid < s) red[tid] = fmaxf(red[tid], red[tid + s]);
        __syncthreads();
    }
    if (tid == 0) mx_s = red[0];
    __syncthreads();
    float m = mx_s, z = 0.f;
    for (int i = tid; i < NN * NN; i += 1024) z += expf(sc[i] - m);
    red[tid] = z;
    __syncthreads();
    for (int s = 512; s; s >>= 1) {
        if (tid < s) red[tid] += red[tid + s];
        __syncthreads();
    }
    if (tid == 0) z_s = red[0];
    __syncthreads();
    float inv = 1.f / z_s;
    for (int i = tid; i < NN * NN; i += 1024)
        g_attw[b * (NN * NN) + i] = expf(sc[i] - m) * inv;
}

// ---------------------------------------------------------------------------
// K4: node aggregation + 3-layer MLP. One block per (b,i) node.
// ---------------------------------------------------------------------------
__global__ void __launch_bounds__(128) k_node(
    const float* __restrict__ Wg1, const float* __restrict__ bg1,
    const float* __restrict__ Wg2, const float* __restrict__ bg2,
    const float* __restrict__ Wout, const float* __restrict__ bout,
    float* __restrict__ out)
{
    __shared__ float nsm[128], g1s[64], g2s[64];
    const int bi = blockIdx.x;
    const int tid = threadIdx.x;
    const int h = tid & 63, half = tid >> 6;

    const float* efa = g_efa + (size_t)bi * NN * HH;
    const float* aw  = g_attw + bi * NN;
    float a = 0.f;
    for (int j = half * 50; j < half * 50 + 50; ++j)
        a += efa[j * 64 + h] * aw[j];
    nsm[tid] = a;
    __syncthreads();
    if (tid < 64) nsm[tid] = nsm[tid] + nsm[tid + 64];
    __syncthreads();
    if (tid < 64) {
        float acc = bg1[tid];
        for (int i = 0; i < 64; ++i) acc += nsm[i] * Wg1[i * 64 + tid];
        g1s[tid] = fmaxf(acc, 0.f);
    }
    __syncthreads();
    if (tid < 64) {
        float acc = bg2[tid];
        for (int i = 0; i < 64; ++i) acc += g1s[i] * Wg2[i * 64 + tid];
        g2s[tid] = fmaxf(acc, 0.f);
    }
    __syncthreads();
    {
        float acc = bout[tid];
        for (int i = 0; i < 64; ++i) acc += g2s[i] * Wout[i * OO + tid];
        out[bi * OO + tid] = fmaxf(acc, 0.f);
    }
}

// ---------------------------------------------------------------------------
extern "C" void kernel_launch(void* const* d_in, const int* in_sizes, int n_in,
                              void* d_out, int out_size) {
    const float* ew   = (const float*)d_in[0];
    const float* We   = (const float*)d_in[1];
    const float* be   = (const float*)d_in[2];
    const float* w1   = (const float*)d_in[3];
    const float* b1   = (const float*)d_in[4];
    const float* w2   = (const float*)d_in[5];
    const float* b2   = (const float*)d_in[6];
    const float* Wt1  = (const float*)d_in[7];
    const float* bt1  = (const float*)d_in[8];
    const float* Wt2  = (const float*)d_in[9];
    const float* bt2  = (const float*)d_in[10];
    const float* Ws1  = (const float*)d_in[11];
    const float* bs1  = (const float*)d_in[12];
    const float* Ws2  = (const float*)d_in[13];
    const float* bs2  = (const float*)d_in[14];
    const float* Wg1  = (const float*)d_in[15];
    const float* bg1  = (const float*)d_in[16];
    const float* Wg2  = (const float*)d_in[17];
    const float* bg2  = (const float*)d_in[18];
    const float* Wout = (const float*)d_in[19];
    const float* bout = (const float*)d_in[20];
    float* out = (float*)d_out;

    const int smem_bytes = S_TOTAL * 4;  // 108032 B
    cudaFuncSetAttribute(k_edge, cudaFuncAttributeMaxDynamicSharedMemorySize,
                         smem_bytes);

    k_prep<<<1, 256>>>(w1, We, be);
    k_edge<<<148, NTHREADS, smem_bytes>>>(ew, b1, w2, b2, Wt1, bt1, Wt2, bt2,
                                          Ws1, bs1, Ws2, bs2);
    k_spatial<<<BB, 1024>>>();
    k_node<<<BB * NN, 128>>>(Wg1, bg1, Wg2, bg2, Wout, bout, out);
}

// round 8
// speedup vs baseline: 6.3758x; 1.0612x over previous
#include <cuda_runtime.h>
#include <cuda_bf16.h>
#include <math.h>
#include <stdint.h>

// Problem constants
#define BB 4
#define NN 100
#define TT 20
#define HH 64
#define OO 128
#define MM 40000            // B*N*N edges
#define NE 8                // edges per group
#define NGROUPS (MM/NE)     // 5000
#define ESLOT 22            // [0]=left pad, [1..20]=t, [21]=right pad
#define XR 200              // row stride (=8 mod 32 for conflict-free MMA gathers)
#define NTHREADS 256
#define NBLOCKS 296         // 2 CTAs per SM

// Scratch
__device__ float g_efa[MM * HH];   // 10.24 MB
__device__ float g_score[MM];
__device__ float g_attw[MM];
__device__ float g_A1[HH * 3];
__device__ float g_Bb[HH * 3];

// ---- helpers ---------------------------------------------------------------
__device__ __forceinline__ float tanha(float x) {
    float y;
    asm("tanh.approx.f32 %0, %1;" : "=f"(y) : "f"(x));
    return y;
}
__device__ __forceinline__ uint32_t f2tf32(float x) {
    uint32_t r;
    asm("cvt.rna.tf32.f32 %0, %1;" : "=r"(r) : "f"(x));
    return r;
}
// pack two f32 -> bf16x2 word; 'lo' lands in low 16 bits (first element)
__device__ __forceinline__ uint32_t pkbf2(float lo, float hi) {
    uint32_t r;
    asm("cvt.rn.bf16x2.f32 %0, %1, %2;" : "=r"(r) : "f"(hi), "f"(lo));
    return r;
}
__device__ __forceinline__ float bfu_lo(uint32_t w) {
    return __uint_as_float(w << 16);
}
__device__ __forceinline__ float bfu_hi(uint32_t w) {
    return __uint_as_float(w & 0xffff0000u);
}
__device__ __forceinline__ void mma_bf16(float d[4], uint4 a,
                                         uint32_t b0, uint32_t b1) {
    asm volatile(
        "mma.sync.aligned.m16n8k16.row.col.f32.bf16.bf16.f32 "
        "{%0,%1,%2,%3},{%4,%5,%6,%7},{%8,%9},{%0,%1,%2,%3};"
        : "+f"(d[0]), "+f"(d[1]), "+f"(d[2]), "+f"(d[3])
        : "r"(a.x), "r"(a.y), "r"(a.z), "r"(a.w), "r"(b0), "r"(b1));
}
__device__ __forceinline__ void mma_tf32(float d[4], uint4 a,
                                         uint32_t b0, uint32_t b1) {
    asm volatile(
        "mma.sync.aligned.m16n8k8.row.col.f32.tf32.tf32.f32 "
        "{%0,%1,%2,%3},{%4,%5,%6,%7},{%8,%9},{%0,%1,%2,%3};"
        : "+f"(d[0]), "+f"(d[1]), "+f"(d[2]), "+f"(d[3])
        : "r"(a.x), "r"(a.y), "r"(a.z), "r"(a.w), "r"(b0), "r"(b1));
}

// ---------------------------------------------------------------------------
// K0: fold conv1 weights against the rank-1 edge embedding
// ---------------------------------------------------------------------------
__global__ void k_prep(const float* __restrict__ w1,
                       const float* __restrict__ We,
                       const float* __restrict__ be) {
    int idx = threadIdx.x;
    if (idx < HH * 3) {
        int h = idx / 3, k = idx % 3;
        float a = 0.f, c = 0.f;
        for (int i = 0; i < HH; ++i) {
            float w = w1[(h * HH + i) * 3 + k];
            a += w * We[i];
            c += w * be[i];
        }
        g_A1[idx] = a;
        g_Bb[idx] = c;
    }
}

// ---------------------------------------------------------------------------
// K2: fused per-edge pipeline; 256 threads, 8 edges/group, 2 CTAs/SM.
// SMEM word offsets:
#define S_W2F  0            // 6144 : conv2 A-frags (bf16x2) [ht][kb12][lane][4]
#define S_WT1F 6144         // 2048 : Wt1 A-frags (bf16x2, sigma-perm)
#define S_WS1F 8192         // 4096 : Ws1 A-frags (tf32)
#define S_XS   12288        // 6400 : packed bf16x2 tile, 32 pair-rows x XR
#define S_ES   18688        // 160
#define S_ATT  18848        // 160
#define S_SPART 19008       // 704  : 4 htiles x 176 (indexed by column)
#define S_EFA  19712        // 544  : 8 edges x 68 (padded stride)
#define S_SS2  20256        // 32
#define S_TOTAL 20288       // words -> 81152 B per CTA
// ---------------------------------------------------------------------------
extern __shared__ float smem[];

__global__ void __launch_bounds__(NTHREADS, 2) k_edge(
    const float* __restrict__ ew,   const float* __restrict__ b1,
    const float* __restrict__ w2,   const float* __restrict__ b2,
    const float* __restrict__ Wt1,  const float* __restrict__ bt1,
    const float* __restrict__ Wt2,  const float* __restrict__ bt2,
    const float* __restrict__ Ws1,  const float* __restrict__ bs1,
    const float* __restrict__ Ws2,  const float* __restrict__ bs2)
{
    uint32_t* w2f  = (uint32_t*)(smem + S_W2F);
    uint32_t* wt1f = (uint32_t*)(smem + S_WT1F);
    float* ws1f  = smem + S_WS1F;
    uint32_t* xsu = (uint32_t*)(smem + S_XS);
    float* e_s   = smem + S_ES;
    float* att_s = smem + S_ATT;
    float* spart = smem + S_SPART;
    float* efa_s = smem + S_EFA;
    float* ss2   = smem + S_SS2;

    const int tid  = threadIdx.x;
    const int w    = tid >> 5;
    const int lane = tid & 31;
    const int htile = w & 3;       // 16 h-rows each
    const int nhalf = w >> 2;      // 0..1, one 4-edge window (80 cols)
    const int gid  = lane >> 2;    // 0..7
    const int tig  = lane & 3;     // 0..3

    // ---- one-time init: conv2 bf16 A-frags ----------------------------------
    for (int f = tid; f < 4 * 12 * 32; f += NTHREADS) {
        int ht = f / 384, rem = f % 384, kb = rem / 32, ln = rem % 32;
        int r = ht * 16 + (ln >> 2);
        int k0 = (ln & 3) * 2;
        int kk = kb >> 2, ibase = (kb & 3) * 16;
        #pragma unroll
        for (int j = 0; j < 4; ++j) {
            int h  = r + (j & 1) * 8;
            int kl = k0 + (j >> 1) * 8;
            float v0 = w2[(h * 64 + ibase + kl) * 3 + kk];
            float v1 = w2[(h * 64 + ibase + kl + 1) * 3 + kk];
            w2f[f * 4 + j] = pkbf2(v0, v1);
        }
    }
    // Wt1 bf16 A-frags with sigma k-permutation (pair P -> h_in pair)
    for (int f = tid; f < 4 * 4 * 32; f += NTHREADS) {
        int ht = f / 128, rem = f % 128, kb = rem / 32, ln = rem % 32;
        int r = ht * 16 + (ln >> 2);
        int tg = ln & 3;
        #pragma unroll
        for (int j = 0; j < 4; ++j) {
            int P = kb * 8 + tg + (j >> 1) * 4;
            int hh = r + (j & 1) * 8;
            int s = (P >> 3) * 16 + (P & 7);
            wt1f[f * 4 + j] = pkbf2(Wt1[s * 64 + hh], Wt1[(s + 8) * 64 + hh]);
        }
    }
    // Ws1 tf32 A-frags
    for (int f = tid; f < 4 * 8 * 32; f += NTHREADS) {
        int ht = f / 256, rem = f % 256, kb = rem / 32, ln = rem % 32;
        int base_r = ht * 16 + (ln >> 2);
        int base_c = kb * 8 + (ln & 3);
        #pragma unroll
        for (int j = 0; j < 4; ++j) {
            int h = base_r + (j & 1) * 8;
            int i = base_c + (j >> 1) * 4;
            ws1f[f * 4 + j] = __uint_as_float(f2tf32(Ws1[i * 64 + h]));
        }
    }
    // zero pad words of the packed tile (32 pair-rows)
    for (int f = tid; f < 32 * 2 * NE; f += NTHREADS) {
        int pr = f / (2 * NE), p = f % (2 * NE);
        int e = p >> 1, side = p & 1;
        xsu[pr * XR + e * ESLOT + side * 21] = 0u;
    }

    // ---- residue-perm column LUTs (conflict-free MMA gathers) ---------------
    // Window = 4 edges (80 valid cols). MMA q, position p take the q-th column
    // in the window with col == p (mod 8). Gather lanes use p=gid; D lanes use
    // p=2*tig, 2*tig+1.
    int cq[10], dc0[10], dc1[10];
    {
        const int wb = nhalf * 4 * ESLOT;
        int n0 = 0, n1 = 0, n2 = 0;
        for (int e4 = 0; e4 < 4; ++e4)
            for (int t = 0; t < TT; ++t) {
                int col = wb + e4 * ESLOT + 1 + t;
                int r8 = col & 7;
                if (r8 == gid)            cq[n0++] = col;
                if (r8 == 2 * tig)        dc0[n1++] = col;
                if (r8 == 2 * tig + 1)    dc1[n2++] = col;
            }
    }
    const int r0 = htile * 16 + gid;   // D rows r0, r0+8
    const float b2_0 = b2[r0],  b2_1 = b2[r0 + 8];
    const float bt1_0 = bt1[r0], bt1_1 = bt1[r0 + 8];
    const float wt2_0 = Wt2[r0], wt2_1 = Wt2[r0 + 8];
    const float bt2v = bt2[0];
    const float bs2v = bs2[0];

    // x1-stage mapping: thread -> channel pair (2pr, 2pr+1), one edge
    const int pr = tid >> 3;           // 0..31
    const int xe = tid & 7;            // edge 0..7
    const int c0 = pr * 2, c1 = c0 + 1;
    float a1k0[3], a1k1[3];
    float s0c = 0.f, s1c = 0.f;
    #pragma unroll
    for (int k = 0; k < 3; ++k) {
        a1k0[k] = g_A1[c0 * 3 + k];  a1k1[k] = g_A1[c1 * 3 + k];
        s0c += g_Bb[c0 * 3 + k];     s1c += g_Bb[c1 * 3 + k];
    }
    const float c3_0 = b1[c0] + s0c;
    const float c3_1 = b1[c1] + s1c;
    const float ca_0 = c3_0 - g_Bb[c0 * 3 + 0];   // t = 0
    const float ca_1 = c3_1 - g_Bb[c1 * 3 + 0];
    const float cb_0 = c3_0 - g_Bb[c0 * 3 + 2];   // t = 19
    const float cb_1 = c3_1 - g_Bb[c1 * 3 + 2];

    // efa-stage mapping: warp covers 8 pair-rows x 4 edges
    const int fpr = (w & 3) * 8 + (lane & 7);     // pair-row 0..31
    const int fe  = (w >> 2) * 4 + (lane >> 3);   // edge 0..7
    const int fh0 = (fpr >> 3) * 16 + (fpr & 7);
    const int fh1 = fh0 + 8;

    // prefetch first group's edge scalars
    float epref = 0.f;
    if (blockIdx.x < NGROUPS && tid < NE * TT)
        epref = ew[blockIdx.x * (NE * TT) + tid];

    for (int g = blockIdx.x; g < NGROUPS; g += gridDim.x) {
        const int m0 = g * NE;

        if (tid < NE * TT) e_s[tid] = epref;
        const int gn = g + gridDim.x;
        if (gn < NGROUPS && tid < NE * TT)
            epref = ew[gn * (NE * TT) + tid];
        __syncthreads();

        // ---- x1 = relu(folded conv1), packed bf16x2 by channel pair ----------
        {
            const float* ep = e_s + xe * TT;
            uint32_t* oa = xsu + pr * XR + xe * ESLOT + 1;
            #pragma unroll
            for (int t = 0; t < TT; ++t) {
                float x0, x1v;
                if (t == 0) {
                    x0 = ca_0 + a1k0[1] * ep[0] + a1k0[2] * ep[1];
                    x1v = ca_1 + a1k1[1] * ep[0] + a1k1[2] * ep[1];
                } else if (t == 19) {
                    x0 = cb_0 + a1k0[0] * ep[18] + a1k0[1] * ep[19];
                    x1v = cb_1 + a1k1[0] * ep[18] + a1k1[1] * ep[19];
                } else {
                    x0 = c3_0 + a1k0[0]*ep[t-1] + a1k0[1]*ep[t] + a1k0[2]*ep[t+1];
                    x1v = c3_1 + a1k1[0]*ep[t-1] + a1k1[1]*ep[t] + a1k1[2]*ep[t+1];
                }
                oa[t] = pkbf2(fmaxf(x0, 0.f), fmaxf(x1v, 0.f));
            }
        }
        __syncthreads();

        // ---- conv2 via bf16 MMA: D[64 x 160], K = 192 (conflict-free B) ------
        float d[10][4];
        #pragma unroll
        for (int q = 0; q < 10; ++q)
            #pragma unroll
            for (int j = 0; j < 4; ++j) d[q][j] = 0.f;

        #pragma unroll 1
        for (int kb = 0; kb < 12; ++kb) {
            const int fo = ((htile * 12 + kb) * 32 + lane) * 4;
            const uint4 A = *(const uint4*)(w2f + fo);
            const int prow = (kb & 3) * 8 + tig;
            const int koff = (kb >> 2) - 1;
            const uint32_t* bp = xsu + prow * XR + koff;
            #pragma unroll
            for (int q = 0; q < 10; ++q) {
                uint32_t b0 = bp[cq[q]];
                uint32_t b1 = bp[cq[q] + 4 * XR];
                mma_bf16(d[q], A, b0, b1);
            }
        }
        __syncthreads();  // all B reads done before overwriting the tile

        // ---- epilogue: x2 = relu(d+b2) packed (r0, r0+8) -> pair-row ----------
        {
            uint32_t* op = xsu + (htile * 8 + gid) * XR;
            #pragma unroll
            for (int q = 0; q < 10; ++q) {
                op[dc0[q]] = pkbf2(fmaxf(d[q][0] + b2_0, 0.f),
                                   fmaxf(d[q][2] + b2_1, 0.f));
                op[dc1[q]] = pkbf2(fmaxf(d[q][1] + b2_0, 0.f),
                                   fmaxf(d[q][3] + b2_1, 0.f));
            }
        }
        __syncthreads();

        // ---- u_pre = Wt1^T @ x2 via bf16 MMA on packed tile -------------------
        float d2[10][4];
        #pragma unroll
        for (int q = 0; q < 10; ++q)
            #pragma unroll
            for (int j = 0; j < 4; ++j) d2[q][j] = 0.f;

        #pragma unroll 1
        for (int kb = 0; kb < 4; ++kb) {
            const int fo = ((htile * 4 + kb) * 32 + lane) * 4;
            const uint4 A = *(const uint4*)(wt1f + fo);
            const uint32_t* bp = xsu + (kb * 8 + tig) * XR;
            #pragma unroll
            for (int q = 0; q < 10; ++q) {
                uint32_t b0 = bp[cq[q]];
                uint32_t b1 = bp[cq[q] + 4 * XR];
                mma_bf16(d2[q], A, b0, b1);
            }
        }

        // ---- score partials (indexed by column) -------------------------------
        #pragma unroll
        for (int q = 0; q < 10; ++q) {
            float s0 = tanha(d2[q][0] + bt1_0) * wt2_0
                     + tanha(d2[q][2] + bt1_1) * wt2_1;
            float s1 = tanha(d2[q][1] + bt1_0) * wt2_0
                     + tanha(d2[q][3] + bt1_1) * wt2_1;
            #pragma unroll
            for (int off = 4; off < 32; off <<= 1) {
                s0 += __shfl_xor_sync(0xffffffffu, s0, off);
                s1 += __shfl_xor_sync(0xffffffffu, s1, off);
            }
            if (lane < 4) {
                spart[htile * 176 + dc0[q]] = s0;
                spart[htile * 176 + dc1[q]] = s1;
            }
        }
        __syncthreads();

        // ---- temporal softmax: warp w handles edge w --------------------------
        {
            float v = -1e30f;
            if (lane < TT) {
                int col = w * ESLOT + 1 + lane;
                v = spart[col] + spart[176 + col] + spart[352 + col]
                  + spart[528 + col] + bt2v;
            }
            float mx = v;
            #pragma unroll
            for (int off = 16; off; off >>= 1)
                mx = fmaxf(mx, __shfl_xor_sync(0xffffffffu, mx, off));
            float ev = (lane < TT) ? expf(v - mx) : 0.f;
            float sum = ev;
            #pragma unroll
            for (int off = 16; off; off >>= 1)
                sum += __shfl_xor_sync(0xffffffffu, sum, off);
            if (lane < TT) att_s[w * TT + lane] = ev / sum;
        }
        __syncthreads();

        // ---- efa: (pair-row, edge) per thread; unpack bf16x2 ------------------
        {
            const uint32_t* xr = xsu + fpr * XR + fe * ESLOT + 1;
            const float* at = att_s + fe * TT;
            float a0 = 0.f, a1 = 0.f;
            #pragma unroll
            for (int t = 0; t < TT; ++t) {
                uint32_t wd = xr[t];
                float av = at[t];
                a0 += bfu_lo(wd) * av;
                a1 += bfu_hi(wd) * av;
            }
            efa_s[fe * 68 + fh0] = a0;
            efa_s[fe * 68 + fh1] = a1;
            g_efa[(m0 + fe) * 64 + fh0] = a0;
            g_efa[(m0 + fe) * 64 + fh1] = a1;
        }
        __syncthreads();

        // ---- spatial score via tf32 MMA: D[64h x 8e], K = 64 ------------------
        if (w < 4) {
            const int ht2 = w;
            float d3[4] = {0.f, 0.f, 0.f, 0.f};
            #pragma unroll
            for (int kb = 0; kb < 8; ++kb) {
                const int fo = ((ht2 * 8 + kb) * 32 + lane) * 4;
                const uint4 A = *(const uint4*)(ws1f + fo);
                const float* bp = efa_s + gid * 68 + kb * 8 + tig;
                uint32_t b0 = __float_as_uint(bp[0]);
                uint32_t b1 = __float_as_uint(bp[4]);
                mma_tf32(d3, A, b0, b1);
            }
            const int rr0 = ht2 * 16 + gid;
            float v0 = tanha(d3[0] + bs1[rr0]) * Ws2[rr0]
                     + tanha(d3[2] + bs1[rr0 + 8]) * Ws2[rr0 + 8];
            float v1 = tanha(d3[1] + bs1[rr0]) * Ws2[rr0]
                     + tanha(d3[3] + bs1[rr0 + 8]) * Ws2[rr0 + 8];
            #pragma unroll
            for (int off = 4; off < 32; off <<= 1) {
                v0 += __shfl_xor_sync(0xffffffffu, v0, off);
                v1 += __shfl_xor_sync(0xffffffffu, v1, off);
            }
            if (lane < 4) {
                int e0 = lane * 2;
                ss2[ht2 * 8 + e0]     = v0;
                ss2[ht2 * 8 + e0 + 1] = v1;
            }
        }
        __syncthreads();
        if (tid < NE)
            g_score[m0 + tid] = ss2[tid] + ss2[8 + tid] + ss2[16 + tid]
                              + ss2[24 + tid] + bs2v;
    }
}

// ---------------------------------------------------------------------------
// K3: per-batch spatial softmax over N*N = 10000 scores
// ---------------------------------------------------------------------------
__global__ void __launch_bounds__(1024) k_spatial() {
    __shared__ float red[1024];
    __shared__ float mx_s, z_s;
    int b = blockIdx.x, tid = threadIdx.x;
    const float* sc = g_score + b * (NN * NN);

    float mx = -1e30f;
    for (int i = tid; i < NN * NN; i += 1024) mx = fmaxf(mx, sc[i]);
    red[tid] = mx;
    __syncthreads();
    for (int s = 512; s; s >>= 1) {
        if (tid < s) red[tid] = fmaxf(red[tid], red[tid + s]);
        __syncthreads();
    }
    if (tid == 0) mx_s = red[0];
    __syncthreads();
    float m = mx_s, z = 0.f;
    for (int i = tid; i < NN * NN; i += 1024) z += expf(sc[i] - m);
    red[tid] = z;
    __syncthreads();
    for (int s = 512; s; s >>= 1) {
        if (tid < s) red[tid] += red[tid + s];
        __syncthreads();
    }
    if (tid == 0) z_s = red[0];
    __syncthreads();
    float inv = 1.f / z_s;
    for (int i = tid; i < NN * NN; i += 1024)
        g_attw[b * (NN * NN) + i] = expf(sc[i] - m) * inv;
}

// ---------------------------------------------------------------------------
// K4: node aggregation + 3-layer MLP. One block per (b,i) node. 256 threads,
// 4-way split of the j-aggregation for latency.
// ---------------------------------------------------------------------------
__global__ void __launch_bounds__(256) k_node(
    const float* __restrict__ Wg1, const float* __restrict__ bg1,
    const float* __restrict__ Wg2, const float* __restrict__ bg2,
    const float* __restrict__ Wout, const float* __restrict__ bout,
    float* __restrict__ out)
{
    __shared__ float nsm[256], g1s[64], g2s[64];
    const int bi = blockIdx.x;
    const int tid = threadIdx.x;
    const int h = tid & 63, quarter = tid >> 6;

    const float* efa = g_efa + (size_t)bi * NN * HH;
    const float* aw  = g_attw + bi * NN;
    float a = 0.f;
    #pragma unroll 5
    for (int j = quarter * 25; j < quarter * 25 + 25; ++j)
        a += efa[j * 64 + h] * aw[j];
    nsm[tid] = a;
    __syncthreads();
    if (tid < 64) {
        float s = nsm[tid] + nsm[tid + 64] + nsm[tid + 128] + nsm[tid + 192];
        nsm[tid] = s;
    }
    __syncthreads();
    if (tid < 64) {
        float acc = bg1[tid];
        for (int i = 0; i < 64; ++i) acc += nsm[i] * Wg1[i * 64 + tid];
        g1s[tid] = fmaxf(acc, 0.f);
    }
    __syncthreads();
    if (tid < 64) {
        float acc = bg2[tid];
        for (int i = 0; i < 64; ++i) acc += g1s[i] * Wg2[i * 64 + tid];
        g2s[tid] = fmaxf(acc, 0.f);
    }
    __syncthreads();
    if (tid < OO) {
        float acc = bout[tid];
        for (int i = 0; i < 64; ++i) acc += g2s[i] * Wout[i * OO + tid];
        out[bi * OO + tid] = fmaxf(acc, 0.f);
    }
}

// ---------------------------------------------------------------------------
extern "C" void kernel_launch(void* const* d_in, const int* in_sizes, int n_in,
                              void* d_out, int out_size) {
    const float* ew   = (const float*)d_in[0];
    const float* We   = (const float*)d_in[1];
    const float* be   = (const float*)d_in[2];
    const float* w1   = (const float*)d_in[3];
    const float* b1   = (const float*)d_in[4];
    const float* w2   = (const float*)d_in[5];
    const float* b2   = (const float*)d_in[6];
    const float* Wt1  = (const float*)d_in[7];
    const float* bt1  = (const float*)d_in[8];
    const float* Wt2  = (const float*)d_in[9];
    const float* bt2  = (const float*)d_in[10];
    const float* Ws1  = (const float*)d_in[11];
    const float* bs1  = (const float*)d_in[12];
    const float* Ws2  = (const float*)d_in[13];
    const float* bs2  = (const float*)d_in[14];
    const float* Wg1  = (const float*)d_in[15];
    const float* bg1  = (const float*)d_in[16];
    const float* Wg2  = (const float*)d_in[17];
    const float* bg2  = (const float*)d_in[18];
    const float* Wout = (const float*)d_in[19];
    const float* bout = (const float*)d_in[20];
    float* out = (float*)d_out;

    const int smem_bytes = S_TOTAL * 4;  // 81152 B per CTA
    cudaFuncSetAttribute(k_edge, cudaFuncAttributeMaxDynamicSharedMemorySize,
                         smem_bytes);

    k_prep<<<1, 256>>>(w1, We, be);
    k_edge<<<NBLOCKS, NTHREADS, smem_bytes>>>(ew, b1, w2, b2, Wt1, bt1,
                                              Wt2, bt2, Ws1, bs1, Ws2, bs2);
    k_spatial<<<BB, 1024>>>();
    k_node<<<BB * NN, 256>>>(Wg1, bg1, Wg2, bg2, Wout, bout, out);
}